// round 2
// baseline (speedup 1.0000x reference)
#include <cuda_runtime.h>
#include <cuda_bf16.h>
#include <math.h>

// ---------------------------------------------------------------------------
// GCN (3-layer) on 100k nodes / 1.6M edges.
//   layer: out = A_hat (x W) + b,  A_hat = D^-1/2 A D^-1/2 + D^-1 I (self loop)
// NOTE: edge_index is int32 on device (JAX x64 disabled -> int64 request is
// silently downcast). Reading it as int64 was the round-1 crash.
// ---------------------------------------------------------------------------

#define CH 256
#define OUTCH 40
#define N_NODES_MAX 100000
#define N_EDGES_MAX 1600000

// scratch (static device memory; no cudaMalloc anywhere)
__device__ float g_h[(size_t)N_NODES_MAX * CH];     // GEMM output
__device__ float g_agg[(size_t)N_NODES_MAX * CH];   // aggregation output
__device__ int   g_cnt[N_NODES_MAX];
__device__ int   g_rowptr[N_NODES_MAX + 1];
__device__ int   g_wptr[N_NODES_MAX];
__device__ float g_dinv[N_NODES_MAX];
__device__ int   g_src_sorted[N_EDGES_MAX];
__device__ float g_norm_sorted[N_EDGES_MAX];

// ------------------------- CSR build -------------------------

__global__ void zero_cnt_kernel(int n) {
    int i = blockIdx.x * blockDim.x + threadIdx.x;
    if (i < n) g_cnt[i] = 0;
}

__global__ void hist_kernel(const int* __restrict__ ei, int E) {
    int e = blockIdx.x * blockDim.x + threadIdx.x;
    if (e < E) {
        int d = ei[E + e];                 // dst row of edge_index (int32!)
        atomicAdd(&g_cnt[d], 1);
    }
}

__global__ void dinv_kernel(int n) {
    int i = blockIdx.x * blockDim.x + threadIdx.x;
    if (i < n) g_dinv[i] = rsqrtf((float)g_cnt[i] + 1.0f);
}

// single-block exclusive scan over g_cnt -> g_rowptr, g_wptr
__global__ void scan_kernel(int n) {
    __shared__ int ssum[1024];
    const int t = threadIdx.x;
    const int CHK = (n + 1023) / 1024;
    int start = t * CHK;
    int end   = min(start + CHK, n);
    int s = 0;
    for (int i = start; i < end; i++) s += g_cnt[i];
    ssum[t] = s;
    __syncthreads();
    for (int off = 1; off < 1024; off <<= 1) {
        int v = 0;
        if (t >= off) v = ssum[t - off];
        __syncthreads();
        if (t >= off) ssum[t] += v;
        __syncthreads();
    }
    int run = (t == 0) ? 0 : ssum[t - 1];
    for (int i = start; i < end; i++) {
        g_rowptr[i] = run;
        g_wptr[i]   = run;
        run += g_cnt[i];
    }
    if (end == n) g_rowptr[n] = run;
}

__global__ void scatter_kernel(const int* __restrict__ ei, int E) {
    int e = blockIdx.x * blockDim.x + threadIdx.x;
    if (e < E) {
        int s = ei[e];
        int d = ei[E + e];
        int pos = atomicAdd(&g_wptr[d], 1);
        g_src_sorted[pos]  = s;
        g_norm_sorted[pos] = g_dinv[s] * g_dinv[d];
    }
}

// ------------------------- SGEMM (fp32, 128x128x8, 8x8 per thread) ---------
// C (= g_h) = A @ B.  SRC_AGG: A comes from g_agg; otherwise from the A param.

template <bool SRC_AGG>
__global__ __launch_bounds__(256) void sgemm_kernel(
    const float* __restrict__ Aparam, const float* __restrict__ B,
    int M, int N, int K)
{
    const float* A = SRC_AGG ? (const float*)g_agg : Aparam;
    constexpr int BM = 128, BN = 128, BK = 8, TM = 8, TN = 8;
    __shared__ float As[BK][BM];
    __shared__ float Bs[BK][BN];

    const int tid = threadIdx.x;
    const int tx  = tid & 15;
    const int ty  = tid >> 4;
    const int m0  = blockIdx.y * BM;
    const int n0  = blockIdx.x * BN;

    const int arow = tid >> 1;
    const int acol = (tid & 1) * 4;
    const int brow = tid >> 5;
    const int bcol = (tid & 31) * 4;

    float acc[TM][TN];
#pragma unroll
    for (int i = 0; i < TM; i++)
#pragma unroll
        for (int j = 0; j < TN; j++) acc[i][j] = 0.0f;

    for (int k0 = 0; k0 < K; k0 += BK) {
        float4 av = make_float4(0.f, 0.f, 0.f, 0.f);
        int gm = m0 + arow;
        if (gm < M) av = *(const float4*)(A + (size_t)gm * K + k0 + acol);
        As[acol + 0][arow] = av.x;
        As[acol + 1][arow] = av.y;
        As[acol + 2][arow] = av.z;
        As[acol + 3][arow] = av.w;

        int gk = k0 + brow;
        int gn = n0 + bcol;
        float4 bv;
        if (gn + 3 < N) {
            bv = *(const float4*)(B + (size_t)gk * N + gn);
        } else {
            float t0 = (gn + 0 < N) ? B[(size_t)gk * N + gn + 0] : 0.f;
            float t1 = (gn + 1 < N) ? B[(size_t)gk * N + gn + 1] : 0.f;
            float t2 = (gn + 2 < N) ? B[(size_t)gk * N + gn + 2] : 0.f;
            float t3 = (gn + 3 < N) ? B[(size_t)gk * N + gn + 3] : 0.f;
            bv = make_float4(t0, t1, t2, t3);
        }
        *(float4*)&Bs[brow][bcol] = bv;
        __syncthreads();

#pragma unroll
        for (int k = 0; k < BK; k++) {
            float a[TM], b[TN];
#pragma unroll
            for (int i = 0; i < TM; i++) a[i] = As[k][ty * TM + i];
#pragma unroll
            for (int j = 0; j < TN; j++) b[j] = Bs[k][tx * TN + j];
#pragma unroll
            for (int i = 0; i < TM; i++)
#pragma unroll
                for (int j = 0; j < TN; j++) acc[i][j] += a[i] * b[j];
        }
        __syncthreads();
    }

#pragma unroll
    for (int i = 0; i < TM; i++) {
        int gm = m0 + ty * TM + i;
        if (gm >= M) continue;
#pragma unroll
        for (int j = 0; j < TN; j++) {
            int gn = n0 + tx * TN + j;
            if (gn < N) g_h[(size_t)gm * N + gn] = acc[i][j];
        }
    }
}

// ------------------------- Aggregation -------------------------
// g_agg[i][c] = sum_{e in row i} norm_e * g_h[src_e][c] + dinv_i^2 * g_h[i][c] + b[c]
template <int C_, bool RELU>
__global__ void aggregate_kernel(const float* __restrict__ bias, int n)
{
    const int node = blockIdx.x;
    const int c = threadIdx.x;
    if (node >= n || c >= C_) return;
    const int beg = g_rowptr[node];
    const int end = g_rowptr[node + 1];
    const float di = g_dinv[node];
    float acc = g_h[(size_t)node * C_ + c] * di * di;
    for (int e = beg; e < end; e++) {
        int   s = __ldg(&g_src_sorted[e]);
        float w = __ldg(&g_norm_sorted[e]);
        acc += w * __ldg(&g_h[(size_t)s * C_ + c]);
    }
    acc += bias[c];
    if (RELU) acc = fmaxf(acc, 0.0f);
    g_agg[(size_t)node * C_ + c] = acc;
}

// ------------------------- log_softmax (40 ch, warp per node) ---------------

__global__ void logsoftmax_kernel(float* __restrict__ out, int n)
{
    int gtid = blockIdx.x * blockDim.x + threadIdx.x;
    int warp = gtid >> 5;
    int lane = gtid & 31;
    if (warp >= n) return;
    const float* v = g_agg + (size_t)warp * OUTCH;
    float x0 = v[lane];
    float x1 = (lane < OUTCH - 32) ? v[32 + lane] : -INFINITY;
    float m = fmaxf(x0, x1);
#pragma unroll
    for (int off = 16; off > 0; off >>= 1)
        m = fmaxf(m, __shfl_xor_sync(0xFFFFFFFF, m, off));
    float s = expf(x0 - m) + ((lane < OUTCH - 32) ? expf(x1 - m) : 0.0f);
#pragma unroll
    for (int off = 16; off > 0; off >>= 1)
        s += __shfl_xor_sync(0xFFFFFFFF, s, off);
    float lse = logf(s);
    float* o = out + (size_t)warp * OUTCH;
    o[lane] = x0 - m - lse;
    if (lane < OUTCH - 32) o[32 + lane] = x1 - m - lse;
}

// ------------------------- launch -------------------------

extern "C" void kernel_launch(void* const* d_in, const int* in_sizes, int n_in,
                              void* d_out, int out_size)
{
    const float* x  = (const float*)d_in[0];
    const int*   ei = (const int*)d_in[1];       // int32 (JAX default)
    const float* W1 = (const float*)d_in[2];
    const float* b1 = (const float*)d_in[3];
    const float* W2 = (const float*)d_in[4];
    const float* b2 = (const float*)d_in[5];
    const float* W3 = (const float*)d_in[6];
    const float* b3 = (const float*)d_in[7];
    float* out = (float*)d_out;

    const int N = in_sizes[0] / CH;       // 100000
    const int E = in_sizes[1] / 2;        // 1600000

    // --- CSR build ---
    zero_cnt_kernel<<<(N + 255) / 256, 256>>>(N);
    hist_kernel<<<(E + 255) / 256, 256>>>(ei, E);
    dinv_kernel<<<(N + 255) / 256, 256>>>(N);
    scan_kernel<<<1, 1024>>>(N);
    scatter_kernel<<<(E + 255) / 256, 256>>>(ei, E);

    dim3 grid256((CH + 127) / 128, (N + 127) / 128);

    // --- layer 1 ---
    sgemm_kernel<false><<<grid256, 256>>>(x, W1, N, CH, CH);
    aggregate_kernel<CH, true><<<N, CH>>>(b1, N);
    // --- layer 2 ---
    sgemm_kernel<true><<<grid256, 256>>>(nullptr, W2, N, CH, CH);
    aggregate_kernel<CH, true><<<N, CH>>>(b2, N);
    // --- layer 3: GEMM (N=40) then aggregate narrow, then log_softmax ---
    {
        dim3 grid(1, (N + 127) / 128);
        sgemm_kernel<true><<<grid, 256>>>(nullptr, W3, N, OUTCH, CH);
        aggregate_kernel<OUTCH, false><<<N, 64>>>(b3, N);
        int blocks = (N * 32 + 255) / 256;
        logsoftmax_kernel<<<blocks, 256>>>(out, N);
    }
}

// round 3
// speedup vs baseline: 1.2821x; 1.2821x over previous
#include <cuda_runtime.h>
#include <cuda_bf16.h>
#include <math.h>

// ---------------------------------------------------------------------------
// GCN (3-layer) on 100k nodes / 1.6M edges.  edge_index arrives int32.
//   layer: out = A_hat (x W) + b,  A_hat = D^-1/2 A D^-1/2 + D^-1 I
// Round-2 passed @1841us. This round: parallel scan (was 161us single-block),
// float4 aggregation, double-buffered BK=16 SGEMM.
// ---------------------------------------------------------------------------

#define CH 256
#define OUTCH 40
#define N_NODES_MAX 100000
#define N_EDGES_MAX 1600000
#define SCAN_CHUNK 1024            // elements per scan block (256 thr x 4)
#define SCAN_NB ((N_NODES_MAX + SCAN_CHUNK - 1) / SCAN_CHUNK)   // 98

// scratch (static device memory; no cudaMalloc anywhere)
__device__ __align__(16) float g_h[(size_t)N_NODES_MAX * CH];
__device__ __align__(16) float g_agg[(size_t)N_NODES_MAX * CH];
__device__ int   g_cnt[N_NODES_MAX];
__device__ int   g_rowptr[N_NODES_MAX + 1];
__device__ int   g_wptr[N_NODES_MAX];
__device__ float g_dinv[N_NODES_MAX];
__device__ int   g_src_sorted[N_EDGES_MAX];
__device__ float g_norm_sorted[N_EDGES_MAX];
__device__ int   g_blocksum[128];
__device__ int   g_blockoff[128];

// ------------------------- CSR build -------------------------

__global__ void zero_cnt_kernel(int n) {
    int i = blockIdx.x * blockDim.x + threadIdx.x;
    if (i < n) g_cnt[i] = 0;
}

__global__ void hist_kernel(const int* __restrict__ ei, int E) {
    int e = blockIdx.x * blockDim.x + threadIdx.x;
    if (e < E) atomicAdd(&g_cnt[ei[E + e]], 1);
}

// phase 1: per-block partial sums of g_cnt
__global__ void scan_partial_kernel(int n) {
    __shared__ int warpsum[8];
    int base = blockIdx.x * SCAN_CHUNK + threadIdx.x * 4;
    int s = 0;
#pragma unroll
    for (int j = 0; j < 4; j++) {
        int i = base + j;
        if (i < n) s += g_cnt[i];
    }
    // block reduce
    int lane = threadIdx.x & 31, w = threadIdx.x >> 5;
#pragma unroll
    for (int off = 16; off > 0; off >>= 1) s += __shfl_xor_sync(0xFFFFFFFF, s, off);
    if (lane == 0) warpsum[w] = s;
    __syncthreads();
    if (threadIdx.x == 0) {
        int t = 0;
#pragma unroll
        for (int k = 0; k < 8; k++) t += warpsum[k];
        g_blocksum[blockIdx.x] = t;
    }
}

// phase 2: single-block exclusive scan of SCAN_NB block sums (<=128)
__global__ void scan_blocks_kernel(int nb) {
    int t = threadIdx.x;                       // 128 threads
    int v = (t < nb) ? g_blocksum[t] : 0;
    int orig = v;
    int lane = t & 31, w = t >> 5;
#pragma unroll
    for (int off = 1; off < 32; off <<= 1) {
        int u = __shfl_up_sync(0xFFFFFFFF, v, off);
        if (lane >= off) v += u;
    }
    __shared__ int ws[4];
    if (lane == 31) ws[w] = v;
    __syncthreads();
    int add = 0;
    for (int k = 0; k < w; k++) add += ws[k];
    if (t < nb) g_blockoff[t] = v + add - orig;   // exclusive
}

// phase 3: emit rowptr/wptr/dinv with block-local scan
__global__ void scan_emit_kernel(int n, int E) {
    __shared__ int warpincl[8];
    int base = blockIdx.x * SCAN_CHUNK + threadIdx.x * 4;
    int c[4];
    int s = 0;
#pragma unroll
    for (int j = 0; j < 4; j++) {
        int i = base + j;
        c[j] = (i < n) ? g_cnt[i] : 0;
        s += c[j];
    }
    int lane = threadIdx.x & 31, w = threadIdx.x >> 5;
    int v = s;
#pragma unroll
    for (int off = 1; off < 32; off <<= 1) {
        int u = __shfl_up_sync(0xFFFFFFFF, v, off);
        if (lane >= off) v += u;
    }
    if (lane == 31) warpincl[w] = v;
    __syncthreads();
    int add = 0;
    for (int k = 0; k < w; k++) add += warpincl[k];
    int run = g_blockoff[blockIdx.x] + add + v - s;   // exclusive prefix
#pragma unroll
    for (int j = 0; j < 4; j++) {
        int i = base + j;
        if (i < n) {
            g_rowptr[i] = run;
            g_wptr[i]   = run;
            g_dinv[i]   = rsqrtf((float)c[j] + 1.0f);
            run += c[j];
        }
    }
    if (blockIdx.x == 0 && threadIdx.x == 0) g_rowptr[n] = E;
}

__global__ void scatter_kernel(const int* __restrict__ ei, int E) {
    int e = blockIdx.x * blockDim.x + threadIdx.x;
    if (e < E) {
        int s = ei[e];
        int d = ei[E + e];
        int pos = atomicAdd(&g_wptr[d], 1);
        g_src_sorted[pos]  = s;
        g_norm_sorted[pos] = g_dinv[s] * g_dinv[d];
    }
}

// ------------------- SGEMM: 128x128x16, 8x8/thread, double-buffered --------

template <bool SRC_AGG>
__global__ __launch_bounds__(256) void sgemm_kernel(
    const float* __restrict__ Aparam, const float* __restrict__ B,
    int M, int N, int K)
{
    const float* A = SRC_AGG ? (const float*)g_agg : Aparam;
    constexpr int BM = 128, BN = 128, BK = 16;
    __shared__ float As[2][BK][BM];
    __shared__ float Bs[2][BK][BN];

    const int tid = threadIdx.x;
    const int tx  = tid & 15;
    const int ty  = tid >> 4;
    const int m0  = blockIdx.y * BM;
    const int n0  = blockIdx.x * BN;

    const int ar = tid >> 2;            // 0..63
    const int ak = (tid & 3) * 4;       // 0,4,8,12
    const int br = tid >> 5;            // 0..7
    const int bc = (tid & 31) * 4;      // 0..124

    float4 aReg[2], bReg[2];

    auto loadTile = [&](int k0) {
#pragma unroll
        for (int p = 0; p < 2; p++) {
            int gm = m0 + ar + p * 64;
            aReg[p] = (gm < M) ? *(const float4*)(A + (size_t)gm * K + k0 + ak)
                               : make_float4(0.f, 0.f, 0.f, 0.f);
            int gk = k0 + br + p * 8;
            int gn = n0 + bc;
            if (gn + 3 < N) {
                bReg[p] = *(const float4*)(B + (size_t)gk * N + gn);
            } else {
                float t0 = (gn + 0 < N) ? B[(size_t)gk * N + gn + 0] : 0.f;
                float t1 = (gn + 1 < N) ? B[(size_t)gk * N + gn + 1] : 0.f;
                float t2 = (gn + 2 < N) ? B[(size_t)gk * N + gn + 2] : 0.f;
                float t3 = (gn + 3 < N) ? B[(size_t)gk * N + gn + 3] : 0.f;
                bReg[p] = make_float4(t0, t1, t2, t3);
            }
        }
    };
    auto storeTile = [&](int buf) {
#pragma unroll
        for (int p = 0; p < 2; p++) {
            int r = ar + p * 64;
            As[buf][ak + 0][r] = aReg[p].x;
            As[buf][ak + 1][r] = aReg[p].y;
            As[buf][ak + 2][r] = aReg[p].z;
            As[buf][ak + 3][r] = aReg[p].w;
            *(float4*)&Bs[buf][br + p * 8][bc] = bReg[p];
        }
    };

    float acc[8][8];
#pragma unroll
    for (int i = 0; i < 8; i++)
#pragma unroll
        for (int j = 0; j < 8; j++) acc[i][j] = 0.0f;

    loadTile(0);
    storeTile(0);
    __syncthreads();

    const int NT = K / BK;
    for (int kt = 0; kt < NT; kt++) {
        int cur = kt & 1;
        if (kt + 1 < NT) loadTile((kt + 1) * BK);
#pragma unroll
        for (int k = 0; k < BK; k++) {
            float a[8], b[8];
            *(float4*)&a[0] = *(const float4*)&As[cur][k][ty * 8];
            *(float4*)&a[4] = *(const float4*)&As[cur][k][ty * 8 + 4];
            *(float4*)&b[0] = *(const float4*)&Bs[cur][k][tx * 8];
            *(float4*)&b[4] = *(const float4*)&Bs[cur][k][tx * 8 + 4];
#pragma unroll
            for (int i = 0; i < 8; i++)
#pragma unroll
                for (int j = 0; j < 8; j++) acc[i][j] += a[i] * b[j];
        }
        if (kt + 1 < NT) storeTile(cur ^ 1);
        __syncthreads();
    }

#pragma unroll
    for (int i = 0; i < 8; i++) {
        int gm = m0 + ty * 8 + i;
        if (gm >= M) continue;
#pragma unroll
        for (int j = 0; j < 8; j++) {
            int gn = n0 + tx * 8 + j;
            if (gn < N) g_h[(size_t)gm * N + gn] = acc[i][j];
        }
    }
}

// ------------------------- Aggregation (256-ch, float4) ---------------------
// 4 nodes per block, 64 threads (float4 lanes) per node.
template <bool RELU>
__global__ __launch_bounds__(256) void aggregate256_kernel(
    const float* __restrict__ bias, int n)
{
    const int node = blockIdx.x * 4 + (threadIdx.x >> 6);
    const int c4   = threadIdx.x & 63;
    if (node >= n) return;
    const float4* h4 = (const float4*)g_h;
    const int beg = g_rowptr[node];
    const int end = g_rowptr[node + 1];
    const float di = g_dinv[node];
    float4 hv = h4[(size_t)node * 64 + c4];
    float dii = di * di;
    float4 acc = make_float4(hv.x * dii, hv.y * dii, hv.z * dii, hv.w * dii);
    for (int e = beg; e < end; e++) {
        int   s = __ldg(&g_src_sorted[e]);
        float w = __ldg(&g_norm_sorted[e]);
        float4 v = __ldg(&h4[(size_t)s * 64 + c4]);
        acc.x += w * v.x; acc.y += w * v.y; acc.z += w * v.z; acc.w += w * v.w;
    }
    float4 bb = ((const float4*)bias)[c4];
    acc.x += bb.x; acc.y += bb.y; acc.z += bb.z; acc.w += bb.w;
    if (RELU) {
        acc.x = fmaxf(acc.x, 0.f); acc.y = fmaxf(acc.y, 0.f);
        acc.z = fmaxf(acc.z, 0.f); acc.w = fmaxf(acc.w, 0.f);
    }
    ((float4*)g_agg)[(size_t)node * 64 + c4] = acc;
}

// narrow (40-ch) aggregation for layer 3
__global__ void aggregate40_kernel(const float* __restrict__ bias, int n)
{
    const int node = blockIdx.x;
    const int c = threadIdx.x;
    if (node >= n || c >= OUTCH) return;
    const int beg = g_rowptr[node];
    const int end = g_rowptr[node + 1];
    const float di = g_dinv[node];
    float acc = g_h[(size_t)node * OUTCH + c] * di * di;
    for (int e = beg; e < end; e++) {
        int   s = __ldg(&g_src_sorted[e]);
        float w = __ldg(&g_norm_sorted[e]);
        acc += w * __ldg(&g_h[(size_t)s * OUTCH + c]);
    }
    g_agg[(size_t)node * OUTCH + c] = acc + bias[c];
}

// ------------------------- log_softmax (40 ch, warp per node) ---------------

__global__ void logsoftmax_kernel(float* __restrict__ out, int n)
{
    int gtid = blockIdx.x * blockDim.x + threadIdx.x;
    int warp = gtid >> 5;
    int lane = gtid & 31;
    if (warp >= n) return;
    const float* v = g_agg + (size_t)warp * OUTCH;
    float x0 = v[lane];
    float x1 = (lane < OUTCH - 32) ? v[32 + lane] : -INFINITY;
    float m = fmaxf(x0, x1);
#pragma unroll
    for (int off = 16; off > 0; off >>= 1)
        m = fmaxf(m, __shfl_xor_sync(0xFFFFFFFF, m, off));
    float s = expf(x0 - m) + ((lane < OUTCH - 32) ? expf(x1 - m) : 0.0f);
#pragma unroll
    for (int off = 16; off > 0; off >>= 1)
        s += __shfl_xor_sync(0xFFFFFFFF, s, off);
    float lse = logf(s);
    float* o = out + (size_t)warp * OUTCH;
    o[lane] = x0 - m - lse;
    if (lane < OUTCH - 32) o[32 + lane] = x1 - m - lse;
}

// ------------------------- launch -------------------------

extern "C" void kernel_launch(void* const* d_in, const int* in_sizes, int n_in,
                              void* d_out, int out_size)
{
    const float* x  = (const float*)d_in[0];
    const int*   ei = (const int*)d_in[1];       // int32
    const float* W1 = (const float*)d_in[2];
    const float* b1 = (const float*)d_in[3];
    const float* W2 = (const float*)d_in[4];
    const float* b2 = (const float*)d_in[5];
    const float* W3 = (const float*)d_in[6];
    const float* b3 = (const float*)d_in[7];
    float* out = (float*)d_out;

    const int N = in_sizes[0] / CH;       // 100000
    const int E = in_sizes[1] / 2;        // 1600000
    const int NB = (N + SCAN_CHUNK - 1) / SCAN_CHUNK;

    // --- CSR build ---
    zero_cnt_kernel<<<(N + 255) / 256, 256>>>(N);
    hist_kernel<<<(E + 255) / 256, 256>>>(ei, E);
    scan_partial_kernel<<<NB, 256>>>(N);
    scan_blocks_kernel<<<1, 128>>>(NB);
    scan_emit_kernel<<<NB, 256>>>(N, E);
    scatter_kernel<<<(E + 255) / 256, 256>>>(ei, E);

    dim3 grid256((CH + 127) / 128, (N + 127) / 128);
    int aggBlocks = (N + 3) / 4;

    // --- layer 1 ---
    sgemm_kernel<false><<<grid256, 256>>>(x, W1, N, CH, CH);
    aggregate256_kernel<true><<<aggBlocks, 256>>>(b1, N);
    // --- layer 2 ---
    sgemm_kernel<true><<<grid256, 256>>>(nullptr, W2, N, CH, CH);
    aggregate256_kernel<true><<<aggBlocks, 256>>>(b2, N);
    // --- layer 3: GEMM (N=40), aggregate narrow, log_softmax ---
    {
        dim3 grid(1, (N + 127) / 128);
        sgemm_kernel<true><<<grid, 256>>>(nullptr, W3, N, OUTCH, CH);
        aggregate40_kernel<<<N, 64>>>(b3, N);
        int blocks = (N * 32 + 255) / 256;
        logsoftmax_kernel<<<blocks, 256>>>(out, N);
    }
}

// round 5
// speedup vs baseline: 2.1532x; 1.6795x over previous
#include <cuda_runtime.h>
#include <cuda_bf16.h>
#include <math.h>
#include <stdint.h>

// ---------------------------------------------------------------------------
// GCN (3-layer) on 100k nodes / 1.6M edges.  edge_index arrives int32.
// R5: tcgen05 unavailable (harness PTX target = compute_103, no 'a' features).
// 256-wide GEMMs use mma.sync m16n8k8 TF32 (sm_80 baseline PTX -> HMMA).
// ---------------------------------------------------------------------------

#define CH 256
#define OUTCH 40
#define N_NODES_MAX 100000
#define N_EDGES_MAX 1600000
#define SCAN_CHUNK 1024

__device__ __align__(16) float g_h[(size_t)N_NODES_MAX * CH];
__device__ __align__(16) float g_agg[(size_t)N_NODES_MAX * CH];
__device__ int   g_cnt[N_NODES_MAX];
__device__ int   g_rowptr[N_NODES_MAX + 1];
__device__ int   g_wptr[N_NODES_MAX];
__device__ float g_dinv[N_NODES_MAX];
__device__ int   g_src_sorted[N_EDGES_MAX];
__device__ float g_norm_sorted[N_EDGES_MAX];
__device__ int   g_blocksum[128];
__device__ int   g_blockoff[128];

// ------------------------- CSR build -------------------------

__global__ void zero_cnt_kernel(int n) {
    int i = blockIdx.x * blockDim.x + threadIdx.x;
    if (i < n) g_cnt[i] = 0;
}
__global__ void hist_kernel(const int* __restrict__ ei, int E) {
    int e = blockIdx.x * blockDim.x + threadIdx.x;
    if (e < E) atomicAdd(&g_cnt[ei[E + e]], 1);
}
__global__ void scan_partial_kernel(int n) {
    __shared__ int warpsum[8];
    int base = blockIdx.x * SCAN_CHUNK + threadIdx.x * 4;
    int s = 0;
#pragma unroll
    for (int j = 0; j < 4; j++) { int i = base + j; if (i < n) s += g_cnt[i]; }
    int lane = threadIdx.x & 31, w = threadIdx.x >> 5;
#pragma unroll
    for (int off = 16; off > 0; off >>= 1) s += __shfl_xor_sync(0xFFFFFFFF, s, off);
    if (lane == 0) warpsum[w] = s;
    __syncthreads();
    if (threadIdx.x == 0) {
        int t = 0;
#pragma unroll
        for (int k = 0; k < 8; k++) t += warpsum[k];
        g_blocksum[blockIdx.x] = t;
    }
}
__global__ void scan_blocks_kernel(int nb) {
    int t = threadIdx.x;
    int v = (t < nb) ? g_blocksum[t] : 0;
    int orig = v;
    int lane = t & 31, w = t >> 5;
#pragma unroll
    for (int off = 1; off < 32; off <<= 1) {
        int u = __shfl_up_sync(0xFFFFFFFF, v, off);
        if (lane >= off) v += u;
    }
    __shared__ int ws[4];
    if (lane == 31) ws[w] = v;
    __syncthreads();
    int add = 0;
    for (int k = 0; k < w; k++) add += ws[k];
    if (t < nb) g_blockoff[t] = v + add - orig;
}
__global__ void scan_emit_kernel(int n, int E) {
    __shared__ int warpincl[8];
    int base = blockIdx.x * SCAN_CHUNK + threadIdx.x * 4;
    int c[4];
    int s = 0;
#pragma unroll
    for (int j = 0; j < 4; j++) {
        int i = base + j;
        c[j] = (i < n) ? g_cnt[i] : 0;
        s += c[j];
    }
    int lane = threadIdx.x & 31, w = threadIdx.x >> 5;
    int v = s;
#pragma unroll
    for (int off = 1; off < 32; off <<= 1) {
        int u = __shfl_up_sync(0xFFFFFFFF, v, off);
        if (lane >= off) v += u;
    }
    if (lane == 31) warpincl[w] = v;
    __syncthreads();
    int add = 0;
    for (int k = 0; k < w; k++) add += warpincl[k];
    int run = g_blockoff[blockIdx.x] + add + v - s;
#pragma unroll
    for (int j = 0; j < 4; j++) {
        int i = base + j;
        if (i < n) {
            g_rowptr[i] = run;
            g_wptr[i]   = run;
            g_dinv[i]   = rsqrtf((float)c[j] + 1.0f);
            run += c[j];
        }
    }
    if (blockIdx.x == 0 && threadIdx.x == 0) g_rowptr[n] = E;
}
__global__ void scatter_kernel(const int* __restrict__ ei, int E) {
    int e = blockIdx.x * blockDim.x + threadIdx.x;
    if (e < E) {
        int s = ei[e];
        int d = ei[E + e];
        int pos = atomicAdd(&g_wptr[d], 1);
        g_src_sorted[pos]  = s;
        g_norm_sorted[pos] = g_dinv[s] * g_dinv[d];
    }
}

// ------------------- TF32 mma.sync GEMM: g_h[M,256] = A[M,256] @ B[256,256] -
// BM=128, BN=128, BK=16. 256 threads = 8 warps in 2(M)x4(N); warp = 64x32.
// A smem [m][k] stride 20 (conflict-free frag loads); B smem [k][n] stride 136.

#define GBM 128
#define GBN 128
#define GBK 16
#define ASTRIDE 20
#define BSTRIDE 136

__device__ __forceinline__ uint32_t f2tf32(float f) {
    uint32_t u;
    asm("cvt.rna.tf32.f32 %0, %1;" : "=r"(u) : "f"(f));
    return u;
}

template <bool SRC_AGG>
__global__ __launch_bounds__(256, 2) void gemm_tf32_mma_kernel(
    const float* __restrict__ Aparam, const float* __restrict__ B, int M)
{
    const float* A = SRC_AGG ? (const float*)g_agg : Aparam;
    __shared__ uint32_t As[2][GBM][ASTRIDE];   // [m][k]
    __shared__ uint32_t Bs[2][GBK][BSTRIDE];   // [k][n]

    const int tid  = threadIdx.x;
    const int wid  = tid >> 5;
    const int lane = tid & 31;
    const int grp  = lane >> 2;    // 0..7
    const int tig  = lane & 3;     // 0..3
    const int wm   = wid & 1;      // 0..1 : 64-row slab
    const int wn   = wid >> 1;     // 0..3 : 32-col slab
    const int m0   = blockIdx.y * GBM;
    const int n0   = blockIdx.x * GBN;

    // global-load mapping (2 float4 per thread per tile, for both A and B)
    // A: idx = tid + i*256 -> row = idx/4 (0..127), c4 = idx%4
    // B: k = idx/32 (0..15), c4 = idx%32
    float4 aReg[2], bReg[2];

    auto loadG = [&](int k0) {
#pragma unroll
        for (int i = 0; i < 2; i++) {
            int idx = tid + i * 256;
            int row = idx >> 2, ac4 = idx & 3;
            int gm = m0 + row;
            aReg[i] = (gm < M)
                ? __ldg((const float4*)(A + (size_t)gm * 256 + k0 + ac4 * 4))
                : make_float4(0.f, 0.f, 0.f, 0.f);
            int bk = idx >> 5, bc4 = idx & 31;
            bReg[i] = __ldg((const float4*)(B + (size_t)(k0 + bk) * 256 + n0 + bc4 * 4));
        }
    };
    auto storeS = [&](int buf) {
#pragma unroll
        for (int i = 0; i < 2; i++) {
            int idx = tid + i * 256;
            int row = idx >> 2, ac4 = idx & 3;
            uint4 av = make_uint4(f2tf32(aReg[i].x), f2tf32(aReg[i].y),
                                  f2tf32(aReg[i].z), f2tf32(aReg[i].w));
            *(uint4*)&As[buf][row][ac4 * 4] = av;
            int bk = idx >> 5, bc4 = idx & 31;
            uint4 bv = make_uint4(f2tf32(bReg[i].x), f2tf32(bReg[i].y),
                                  f2tf32(bReg[i].z), f2tf32(bReg[i].w));
            *(uint4*)&Bs[buf][bk][bc4 * 4] = bv;
        }
    };

    float acc[4][4][4];
#pragma unroll
    for (int mt = 0; mt < 4; mt++)
#pragma unroll
        for (int nt = 0; nt < 4; nt++)
#pragma unroll
            for (int r = 0; r < 4; r++) acc[mt][nt][r] = 0.0f;

    loadG(0);
    storeS(0);
    __syncthreads();

    const int NT = 256 / GBK;   // 16
    for (int kt = 0; kt < NT; kt++) {
        const int cur = kt & 1;
        if (kt + 1 < NT) loadG((kt + 1) * GBK);

#pragma unroll
        for (int ks = 0; ks < 2; ks++) {
            const int kk = ks * 8 + tig;
            uint32_t af[4][4], bf[4][2];
#pragma unroll
            for (int mt = 0; mt < 4; mt++) {
                int mr = wm * 64 + mt * 16 + grp;
                af[mt][0] = As[cur][mr][kk];
                af[mt][1] = As[cur][mr + 8][kk];
                af[mt][2] = As[cur][mr][kk + 4];
                af[mt][3] = As[cur][mr + 8][kk + 4];
            }
#pragma unroll
            for (int nt = 0; nt < 4; nt++) {
                int nc = wn * 32 + nt * 8 + grp;
                bf[nt][0] = Bs[cur][kk][nc];
                bf[nt][1] = Bs[cur][kk + 4][nc];
            }
#pragma unroll
            for (int mt = 0; mt < 4; mt++)
#pragma unroll
                for (int nt = 0; nt < 4; nt++) {
                    asm volatile(
                        "mma.sync.aligned.m16n8k8.row.col.f32.tf32.tf32.f32 "
                        "{%0,%1,%2,%3}, {%4,%5,%6,%7}, {%8,%9}, {%0,%1,%2,%3};"
                        : "+f"(acc[mt][nt][0]), "+f"(acc[mt][nt][1]),
                          "+f"(acc[mt][nt][2]), "+f"(acc[mt][nt][3])
                        : "r"(af[mt][0]), "r"(af[mt][1]), "r"(af[mt][2]), "r"(af[mt][3]),
                          "r"(bf[nt][0]), "r"(bf[nt][1]));
                }
        }
        if (kt + 1 < NT) storeS(cur ^ 1);
        __syncthreads();
    }

    // epilogue
#pragma unroll
    for (int mt = 0; mt < 4; mt++) {
        int gm = m0 + wm * 64 + mt * 16 + grp;
#pragma unroll
        for (int nt = 0; nt < 4; nt++) {
            int gn = n0 + wn * 32 + nt * 8 + tig * 2;
            if (gm < M)
                *(float2*)(g_h + (size_t)gm * 256 + gn) =
                    make_float2(acc[mt][nt][0], acc[mt][nt][1]);
            if (gm + 8 < M)
                *(float2*)(g_h + (size_t)(gm + 8) * 256 + gn) =
                    make_float2(acc[mt][nt][2], acc[mt][nt][3]);
        }
    }
}

// ------------------- fp32 SGEMM for layer 3 (N=40), A = g_agg ---------------

__global__ __launch_bounds__(256) void sgemm_kernel(
    const float* __restrict__ B, int M, int N, int K)
{
    const float* A = (const float*)g_agg;
    constexpr int BM = 128, BN = 128, BK = 16;
    __shared__ float As[2][BK][BM];
    __shared__ float Bs[2][BK][BN];

    const int tid = threadIdx.x;
    const int tx  = tid & 15;
    const int ty  = tid >> 4;
    const int m0  = blockIdx.y * BM;
    const int n0  = blockIdx.x * BN;

    const int ar = tid >> 2;
    const int ak = (tid & 3) * 4;
    const int br = tid >> 5;
    const int bc = (tid & 31) * 4;

    float4 aReg[2], bReg[2];
    auto loadTile = [&](int k0) {
#pragma unroll
        for (int p = 0; p < 2; p++) {
            int gm = m0 + ar + p * 64;
            aReg[p] = (gm < M) ? *(const float4*)(A + (size_t)gm * K + k0 + ak)
                               : make_float4(0.f, 0.f, 0.f, 0.f);
            int gk = k0 + br + p * 8;
            int gn = n0 + bc;
            if (gn + 3 < N) {
                bReg[p] = *(const float4*)(B + (size_t)gk * N + gn);
            } else {
                float t0 = (gn + 0 < N) ? B[(size_t)gk * N + gn + 0] : 0.f;
                float t1 = (gn + 1 < N) ? B[(size_t)gk * N + gn + 1] : 0.f;
                float t2 = (gn + 2 < N) ? B[(size_t)gk * N + gn + 2] : 0.f;
                float t3 = (gn + 3 < N) ? B[(size_t)gk * N + gn + 3] : 0.f;
                bReg[p] = make_float4(t0, t1, t2, t3);
            }
        }
    };
    auto storeTile = [&](int buf) {
#pragma unroll
        for (int p = 0; p < 2; p++) {
            int r = ar + p * 64;
            As[buf][ak + 0][r] = aReg[p].x;
            As[buf][ak + 1][r] = aReg[p].y;
            As[buf][ak + 2][r] = aReg[p].z;
            As[buf][ak + 3][r] = aReg[p].w;
            *(float4*)&Bs[buf][br + p * 8][bc] = bReg[p];
        }
    };

    float acc[8][8];
#pragma unroll
    for (int i = 0; i < 8; i++)
#pragma unroll
        for (int j = 0; j < 8; j++) acc[i][j] = 0.0f;

    loadTile(0);
    storeTile(0);
    __syncthreads();

    const int NTt = K / BK;
    for (int kt = 0; kt < NTt; kt++) {
        int cur = kt & 1;
        if (kt + 1 < NTt) loadTile((kt + 1) * BK);
#pragma unroll
        for (int k = 0; k < BK; k++) {
            float a[8], b[8];
            *(float4*)&a[0] = *(const float4*)&As[cur][k][ty * 8];
            *(float4*)&a[4] = *(const float4*)&As[cur][k][ty * 8 + 4];
            *(float4*)&b[0] = *(const float4*)&Bs[cur][k][tx * 8];
            *(float4*)&b[4] = *(const float4*)&Bs[cur][k][tx * 8 + 4];
#pragma unroll
            for (int i = 0; i < 8; i++)
#pragma unroll
                for (int j = 0; j < 8; j++) acc[i][j] += a[i] * b[j];
        }
        if (kt + 1 < NTt) storeTile(cur ^ 1);
        __syncthreads();
    }

#pragma unroll
    for (int i = 0; i < 8; i++) {
        int gm = m0 + ty * 8 + i;
        if (gm >= M) continue;
#pragma unroll
        for (int j = 0; j < 8; j++) {
            int gn = n0 + tx * 8 + j;
            if (gn < N) g_h[(size_t)gm * N + gn] = acc[i][j];
        }
    }
}

// ------------------------- Aggregation (256-ch, float4) ---------------------
template <bool RELU>
__global__ __launch_bounds__(256) void aggregate256_kernel(
    const float* __restrict__ bias, int n)
{
    const int node = blockIdx.x * 4 + (threadIdx.x >> 6);
    const int c4   = threadIdx.x & 63;
    if (node >= n) return;
    const float4* h4 = (const float4*)g_h;
    const int beg = g_rowptr[node];
    const int end = g_rowptr[node + 1];
    const float di = g_dinv[node];
    float4 hv = h4[(size_t)node * 64 + c4];
    float dii = di * di;
    float4 acc = make_float4(hv.x * dii, hv.y * dii, hv.z * dii, hv.w * dii);
    for (int e = beg; e < end; e++) {
        int   s = __ldg(&g_src_sorted[e]);
        float w = __ldg(&g_norm_sorted[e]);
        float4 v = __ldg(&h4[(size_t)s * 64 + c4]);
        acc.x += w * v.x; acc.y += w * v.y; acc.z += w * v.z; acc.w += w * v.w;
    }
    float4 bb = ((const float4*)bias)[c4];
    acc.x += bb.x; acc.y += bb.y; acc.z += bb.z; acc.w += bb.w;
    if (RELU) {
        acc.x = fmaxf(acc.x, 0.f); acc.y = fmaxf(acc.y, 0.f);
        acc.z = fmaxf(acc.z, 0.f); acc.w = fmaxf(acc.w, 0.f);
    }
    ((float4*)g_agg)[(size_t)node * 64 + c4] = acc;
}

__global__ void aggregate40_kernel(const float* __restrict__ bias, int n)
{
    const int node = blockIdx.x;
    const int c = threadIdx.x;
    if (node >= n || c >= OUTCH) return;
    const int beg = g_rowptr[node];
    const int end = g_rowptr[node + 1];
    const float di = g_dinv[node];
    float acc = g_h[(size_t)node * OUTCH + c] * di * di;
    for (int e = beg; e < end; e++) {
        int   s = __ldg(&g_src_sorted[e]);
        float w = __ldg(&g_norm_sorted[e]);
        acc += w * __ldg(&g_h[(size_t)s * OUTCH + c]);
    }
    g_agg[(size_t)node * OUTCH + c] = acc + bias[c];
}

// ------------------------- log_softmax --------------------------------------

__global__ void logsoftmax_kernel(float* __restrict__ out, int n)
{
    int gtid = blockIdx.x * blockDim.x + threadIdx.x;
    int warp = gtid >> 5;
    int lane = gtid & 31;
    if (warp >= n) return;
    const float* v = g_agg + (size_t)warp * OUTCH;
    float x0 = v[lane];
    float x1 = (lane < OUTCH - 32) ? v[32 + lane] : -INFINITY;
    float m = fmaxf(x0, x1);
#pragma unroll
    for (int off = 16; off > 0; off >>= 1)
        m = fmaxf(m, __shfl_xor_sync(0xFFFFFFFF, m, off));
    float s = expf(x0 - m) + ((lane < OUTCH - 32) ? expf(x1 - m) : 0.0f);
#pragma unroll
    for (int off = 16; off > 0; off >>= 1)
        s += __shfl_xor_sync(0xFFFFFFFF, s, off);
    float lse = logf(s);
    float* o = out + (size_t)warp * OUTCH;
    o[lane] = x0 - m - lse;
    if (lane < OUTCH - 32) o[32 + lane] = x1 - m - lse;
}

// ------------------------- launch -------------------------

extern "C" void kernel_launch(void* const* d_in, const int* in_sizes, int n_in,
                              void* d_out, int out_size)
{
    const float* x  = (const float*)d_in[0];
    const int*   ei = (const int*)d_in[1];       // int32
    const float* W1 = (const float*)d_in[2];
    const float* b1 = (const float*)d_in[3];
    const float* W2 = (const float*)d_in[4];
    const float* b2 = (const float*)d_in[5];
    const float* W3 = (const float*)d_in[6];
    const float* b3 = (const float*)d_in[7];
    float* out = (float*)d_out;

    const int N = in_sizes[0] / CH;       // 100000
    const int E = in_sizes[1] / 2;        // 1600000
    const int NB = (N + SCAN_CHUNK - 1) / SCAN_CHUNK;

    // --- CSR build ---
    zero_cnt_kernel<<<(N + 255) / 256, 256>>>(N);
    hist_kernel<<<(E + 255) / 256, 256>>>(ei, E);
    scan_partial_kernel<<<NB, 256>>>(N);
    scan_blocks_kernel<<<1, 128>>>(NB);
    scan_emit_kernel<<<NB, 256>>>(N, E);
    scatter_kernel<<<(E + 255) / 256, 256>>>(ei, E);

    dim3 gemmGrid(CH / GBN, (N + GBM - 1) / GBM);   // (2, 782)
    const int aggBlocks = (N + 3) / 4;

    // --- layer 1 ---
    gemm_tf32_mma_kernel<false><<<gemmGrid, 256>>>(x, W1, N);
    aggregate256_kernel<true><<<aggBlocks, 256>>>(b1, N);
    // --- layer 2 ---
    gemm_tf32_mma_kernel<true><<<gemmGrid, 256>>>(nullptr, W2, N);
    aggregate256_kernel<true><<<aggBlocks, 256>>>(b2, N);
    // --- layer 3: fp32 GEMM (N=40), aggregate narrow, log_softmax ---
    {
        dim3 grid(1, (N + 127) / 128);
        sgemm_kernel<<<grid, 256>>>(W3, N, OUTCH, CH);
        aggregate40_kernel<<<N, 64>>>(b3, N);
        int blocks = (N * 32 + 255) / 256;
        logsoftmax_kernel<<<blocks, 256>>>(out, N);
    }
}

// round 6
// speedup vs baseline: 2.5908x; 1.2032x over previous
#include <cuda_runtime.h>
#include <cuda_fp16.h>
#include <math.h>
#include <stdint.h>

// ---------------------------------------------------------------------------
// GCN (3-layer) on 100k nodes / 1.6M edges.  edge_index arrives int32.
// R6: h (GEMM output, gather source) stored fp16 -> halves aggregation gather
// traffic. Accumulation fp32; g_agg (GEMM input) stays fp32.
// ---------------------------------------------------------------------------

#define CH 256
#define OUTCH 40
#define N_NODES_MAX 100000
#define N_EDGES_MAX 1600000
#define SCAN_CHUNK 1024

__device__ __align__(16) __half g_h16[(size_t)N_NODES_MAX * CH];   // 50 MB
__device__ __align__(16) float  g_agg[(size_t)N_NODES_MAX * CH];   // 100 MB
__device__ int   g_cnt[N_NODES_MAX];
__device__ int   g_rowptr[N_NODES_MAX + 1];
__device__ int   g_wptr[N_NODES_MAX];
__device__ float g_dinv[N_NODES_MAX];
__device__ int   g_src_sorted[N_EDGES_MAX];
__device__ float g_norm_sorted[N_EDGES_MAX];
__device__ int   g_blocksum[128];
__device__ int   g_blockoff[128];

// ------------------------- CSR build -------------------------

__global__ void zero_cnt_kernel(int n) {
    int i = blockIdx.x * blockDim.x + threadIdx.x;
    if (i < n) g_cnt[i] = 0;
}
__global__ void hist_kernel(const int* __restrict__ ei, int E) {
    int e = blockIdx.x * blockDim.x + threadIdx.x;
    if (e < E) atomicAdd(&g_cnt[ei[E + e]], 1);
}
__global__ void scan_partial_kernel(int n) {
    __shared__ int warpsum[8];
    int base = blockIdx.x * SCAN_CHUNK + threadIdx.x * 4;
    int s = 0;
#pragma unroll
    for (int j = 0; j < 4; j++) { int i = base + j; if (i < n) s += g_cnt[i]; }
    int lane = threadIdx.x & 31, w = threadIdx.x >> 5;
#pragma unroll
    for (int off = 16; off > 0; off >>= 1) s += __shfl_xor_sync(0xFFFFFFFF, s, off);
    if (lane == 0) warpsum[w] = s;
    __syncthreads();
    if (threadIdx.x == 0) {
        int t = 0;
#pragma unroll
        for (int k = 0; k < 8; k++) t += warpsum[k];
        g_blocksum[blockIdx.x] = t;
    }
}
__global__ void scan_blocks_kernel(int nb) {
    int t = threadIdx.x;
    int v = (t < nb) ? g_blocksum[t] : 0;
    int orig = v;
    int lane = t & 31, w = t >> 5;
#pragma unroll
    for (int off = 1; off < 32; off <<= 1) {
        int u = __shfl_up_sync(0xFFFFFFFF, v, off);
        if (lane >= off) v += u;
    }
    __shared__ int ws[4];
    if (lane == 31) ws[w] = v;
    __syncthreads();
    int add = 0;
    for (int k = 0; k < w; k++) add += ws[k];
    if (t < nb) g_blockoff[t] = v + add - orig;
}
__global__ void scan_emit_kernel(int n, int E) {
    __shared__ int warpincl[8];
    int base = blockIdx.x * SCAN_CHUNK + threadIdx.x * 4;
    int c[4];
    int s = 0;
#pragma unroll
    for (int j = 0; j < 4; j++) {
        int i = base + j;
        c[j] = (i < n) ? g_cnt[i] : 0;
        s += c[j];
    }
    int lane = threadIdx.x & 31, w = threadIdx.x >> 5;
    int v = s;
#pragma unroll
    for (int off = 1; off < 32; off <<= 1) {
        int u = __shfl_up_sync(0xFFFFFFFF, v, off);
        if (lane >= off) v += u;
    }
    if (lane == 31) warpincl[w] = v;
    __syncthreads();
    int add = 0;
    for (int k = 0; k < w; k++) add += warpincl[k];
    int run = g_blockoff[blockIdx.x] + add + v - s;
#pragma unroll
    for (int j = 0; j < 4; j++) {
        int i = base + j;
        if (i < n) {
            g_rowptr[i] = run;
            g_wptr[i]   = run;
            g_dinv[i]   = rsqrtf((float)c[j] + 1.0f);
            run += c[j];
        }
    }
    if (blockIdx.x == 0 && threadIdx.x == 0) g_rowptr[n] = E;
}
__global__ void scatter_kernel(const int* __restrict__ ei, int E) {
    int e = blockIdx.x * blockDim.x + threadIdx.x;
    if (e < E) {
        int s = ei[e];
        int d = ei[E + e];
        int pos = atomicAdd(&g_wptr[d], 1);
        g_src_sorted[pos]  = s;
        g_norm_sorted[pos] = g_dinv[s] * g_dinv[d];
    }
}

// ------------------- TF32 mma.sync GEMM: g_h16[M,256] = A[M,256] @ B[256,256]
// BM=128, BN=128, BK=16. 8 warps in 2(M)x4(N); warp tile = 64x32.

#define GBM 128
#define GBN 128
#define GBK 16
#define ASTRIDE 20
#define BSTRIDE 136

__device__ __forceinline__ uint32_t f2tf32(float f) {
    uint32_t u;
    asm("cvt.rna.tf32.f32 %0, %1;" : "=r"(u) : "f"(f));
    return u;
}

template <bool SRC_AGG>
__global__ __launch_bounds__(256, 2) void gemm_tf32_mma_kernel(
    const float* __restrict__ Aparam, const float* __restrict__ B, int M)
{
    const float* A = SRC_AGG ? (const float*)g_agg : Aparam;
    __shared__ uint32_t As[2][GBM][ASTRIDE];   // [m][k]
    __shared__ uint32_t Bs[2][GBK][BSTRIDE];   // [k][n]

    const int tid  = threadIdx.x;
    const int wid  = tid >> 5;
    const int lane = tid & 31;
    const int grp  = lane >> 2;
    const int tig  = lane & 3;
    const int wm   = wid & 1;
    const int wn   = wid >> 1;
    const int m0   = blockIdx.y * GBM;
    const int n0   = blockIdx.x * GBN;

    float4 aReg[2], bReg[2];

    auto loadG = [&](int k0) {
#pragma unroll
        for (int i = 0; i < 2; i++) {
            int idx = tid + i * 256;
            int row = idx >> 2, ac4 = idx & 3;
            int gm = m0 + row;
            aReg[i] = (gm < M)
                ? __ldg((const float4*)(A + (size_t)gm * 256 + k0 + ac4 * 4))
                : make_float4(0.f, 0.f, 0.f, 0.f);
            int bk = idx >> 5, bc4 = idx & 31;
            bReg[i] = __ldg((const float4*)(B + (size_t)(k0 + bk) * 256 + n0 + bc4 * 4));
        }
    };
    auto storeS = [&](int buf) {
#pragma unroll
        for (int i = 0; i < 2; i++) {
            int idx = tid + i * 256;
            int row = idx >> 2, ac4 = idx & 3;
            uint4 av = make_uint4(f2tf32(aReg[i].x), f2tf32(aReg[i].y),
                                  f2tf32(aReg[i].z), f2tf32(aReg[i].w));
            *(uint4*)&As[buf][row][ac4 * 4] = av;
            int bk = idx >> 5, bc4 = idx & 31;
            uint4 bv = make_uint4(f2tf32(bReg[i].x), f2tf32(bReg[i].y),
                                  f2tf32(bReg[i].z), f2tf32(bReg[i].w));
            *(uint4*)&Bs[buf][bk][bc4 * 4] = bv;
        }
    };

    float acc[4][4][4];
#pragma unroll
    for (int mt = 0; mt < 4; mt++)
#pragma unroll
        for (int nt = 0; nt < 4; nt++)
#pragma unroll
            for (int r = 0; r < 4; r++) acc[mt][nt][r] = 0.0f;

    loadG(0);
    storeS(0);
    __syncthreads();

    const int NT = 256 / GBK;
    for (int kt = 0; kt < NT; kt++) {
        const int cur = kt & 1;
        if (kt + 1 < NT) loadG((kt + 1) * GBK);

#pragma unroll
        for (int ks = 0; ks < 2; ks++) {
            const int kk = ks * 8 + tig;
            uint32_t af[4][4], bf[4][2];
#pragma unroll
            for (int mt = 0; mt < 4; mt++) {
                int mr = wm * 64 + mt * 16 + grp;
                af[mt][0] = As[cur][mr][kk];
                af[mt][1] = As[cur][mr + 8][kk];
                af[mt][2] = As[cur][mr][kk + 4];
                af[mt][3] = As[cur][mr + 8][kk + 4];
            }
#pragma unroll
            for (int nt = 0; nt < 4; nt++) {
                int nc = wn * 32 + nt * 8 + grp;
                bf[nt][0] = Bs[cur][kk][nc];
                bf[nt][1] = Bs[cur][kk + 4][nc];
            }
#pragma unroll
            for (int mt = 0; mt < 4; mt++)
#pragma unroll
                for (int nt = 0; nt < 4; nt++) {
                    asm volatile(
                        "mma.sync.aligned.m16n8k8.row.col.f32.tf32.tf32.f32 "
                        "{%0,%1,%2,%3}, {%4,%5,%6,%7}, {%8,%9}, {%0,%1,%2,%3};"
                        : "+f"(acc[mt][nt][0]), "+f"(acc[mt][nt][1]),
                          "+f"(acc[mt][nt][2]), "+f"(acc[mt][nt][3])
                        : "r"(af[mt][0]), "r"(af[mt][1]), "r"(af[mt][2]), "r"(af[mt][3]),
                          "r"(bf[nt][0]), "r"(bf[nt][1]));
                }
        }
        if (kt + 1 < NT) storeS(cur ^ 1);
        __syncthreads();
    }

    // epilogue: convert to fp16, store half2
#pragma unroll
    for (int mt = 0; mt < 4; mt++) {
        int gm = m0 + wm * 64 + mt * 16 + grp;
#pragma unroll
        for (int nt = 0; nt < 4; nt++) {
            int gn = n0 + wn * 32 + nt * 8 + tig * 2;
            if (gm < M) {
                __half2 v = __floats2half2_rn(acc[mt][nt][0], acc[mt][nt][1]);
                *(__half2*)(g_h16 + (size_t)gm * 256 + gn) = v;
            }
            if (gm + 8 < M) {
                __half2 v = __floats2half2_rn(acc[mt][nt][2], acc[mt][nt][3]);
                *(__half2*)(g_h16 + (size_t)(gm + 8) * 256 + gn) = v;
            }
        }
    }
}

// ------------------- fp32 SGEMM for layer 3 (N=40), A = g_agg, C = g_h16 ----

__global__ __launch_bounds__(256) void sgemm_kernel(
    const float* __restrict__ B, int M, int N, int K)
{
    const float* A = (const float*)g_agg;
    constexpr int BM = 128, BN = 128, BK = 16;
    __shared__ float As[2][BK][BM];
    __shared__ float Bs[2][BK][BN];

    const int tid = threadIdx.x;
    const int tx  = tid & 15;
    const int ty  = tid >> 4;
    const int m0  = blockIdx.y * BM;
    const int n0  = blockIdx.x * BN;

    const int ar = tid >> 2;
    const int ak = (tid & 3) * 4;
    const int br = tid >> 5;
    const int bc = (tid & 31) * 4;

    float4 aReg[2], bReg[2];
    auto loadTile = [&](int k0) {
#pragma unroll
        for (int p = 0; p < 2; p++) {
            int gm = m0 + ar + p * 64;
            aReg[p] = (gm < M) ? *(const float4*)(A + (size_t)gm * K + k0 + ak)
                               : make_float4(0.f, 0.f, 0.f, 0.f);
            int gk = k0 + br + p * 8;
            int gn = n0 + bc;
            if (gn + 3 < N) {
                bReg[p] = *(const float4*)(B + (size_t)gk * N + gn);
            } else {
                float t0 = (gn + 0 < N) ? B[(size_t)gk * N + gn + 0] : 0.f;
                float t1 = (gn + 1 < N) ? B[(size_t)gk * N + gn + 1] : 0.f;
                float t2 = (gn + 2 < N) ? B[(size_t)gk * N + gn + 2] : 0.f;
                float t3 = (gn + 3 < N) ? B[(size_t)gk * N + gn + 3] : 0.f;
                bReg[p] = make_float4(t0, t1, t2, t3);
            }
        }
    };
    auto storeTile = [&](int buf) {
#pragma unroll
        for (int p = 0; p < 2; p++) {
            int r = ar + p * 64;
            As[buf][ak + 0][r] = aReg[p].x;
            As[buf][ak + 1][r] = aReg[p].y;
            As[buf][ak + 2][r] = aReg[p].z;
            As[buf][ak + 3][r] = aReg[p].w;
            *(float4*)&Bs[buf][br + p * 8][bc] = bReg[p];
        }
    };

    float acc[8][8];
#pragma unroll
    for (int i = 0; i < 8; i++)
#pragma unroll
        for (int j = 0; j < 8; j++) acc[i][j] = 0.0f;

    loadTile(0);
    storeTile(0);
    __syncthreads();

    const int NTt = K / BK;
    for (int kt = 0; kt < NTt; kt++) {
        int cur = kt & 1;
        if (kt + 1 < NTt) loadTile((kt + 1) * BK);
#pragma unroll
        for (int k = 0; k < BK; k++) {
            float a[8], b[8];
            *(float4*)&a[0] = *(const float4*)&As[cur][k][ty * 8];
            *(float4*)&a[4] = *(const float4*)&As[cur][k][ty * 8 + 4];
            *(float4*)&b[0] = *(const float4*)&Bs[cur][k][tx * 8];
            *(float4*)&b[4] = *(const float4*)&Bs[cur][k][tx * 8 + 4];
#pragma unroll
            for (int i = 0; i < 8; i++)
#pragma unroll
                for (int j = 0; j < 8; j++) acc[i][j] += a[i] * b[j];
        }
        if (kt + 1 < NTt) storeTile(cur ^ 1);
        __syncthreads();
    }

#pragma unroll
    for (int i = 0; i < 8; i++) {
        int gm = m0 + ty * 8 + i;
        if (gm >= M) continue;
#pragma unroll
        for (int j = 0; j < 8; j++) {
            int gn = n0 + tx * 8 + j;
            if (gn < N) g_h16[(size_t)gm * N + gn] = __float2half_rn(acc[i][j]);
        }
    }
}

// ------------------- Aggregation 256-ch from fp16 h -------------------------
// 8 nodes/block, 32 threads/node; thread gathers uint4 = 8 halves (16B).
template <bool RELU>
__global__ __launch_bounds__(256) void aggregate256_kernel(
    const float* __restrict__ bias, int n)
{
    const int node = blockIdx.x * 8 + (threadIdx.x >> 5);
    const int c8   = threadIdx.x & 31;            // 16B chunk index
    if (node >= n) return;
    const uint4* h = (const uint4*)g_h16;         // row = 32 uint4
    const int beg = g_rowptr[node];
    const int end = g_rowptr[node + 1];
    const float di = g_dinv[node];
    const float dii = di * di;

    float acc[8];
    {
        uint4 v = h[(size_t)node * 32 + c8];
        const __half2* hp = (const __half2*)&v;
#pragma unroll
        for (int q = 0; q < 4; q++) {
            float2 f = __half22float2(hp[q]);
            acc[q * 2 + 0] = f.x * dii;
            acc[q * 2 + 1] = f.y * dii;
        }
    }

    int e = beg;
    for (; e + 2 <= end; e += 2) {
        int   s0 = __ldg(&g_src_sorted[e]);
        int   s1 = __ldg(&g_src_sorted[e + 1]);
        float w0 = __ldg(&g_norm_sorted[e]);
        float w1 = __ldg(&g_norm_sorted[e + 1]);
        uint4 v0 = __ldg(&h[(size_t)s0 * 32 + c8]);
        uint4 v1 = __ldg(&h[(size_t)s1 * 32 + c8]);
        const __half2* p0 = (const __half2*)&v0;
        const __half2* p1 = (const __half2*)&v1;
#pragma unroll
        for (int q = 0; q < 4; q++) {
            float2 f0 = __half22float2(p0[q]);
            float2 f1 = __half22float2(p1[q]);
            acc[q * 2 + 0] += w0 * f0.x + w1 * f1.x;
            acc[q * 2 + 1] += w0 * f0.y + w1 * f1.y;
        }
    }
    if (e < end) {
        int   s0 = __ldg(&g_src_sorted[e]);
        float w0 = __ldg(&g_norm_sorted[e]);
        uint4 v0 = __ldg(&h[(size_t)s0 * 32 + c8]);
        const __half2* p0 = (const __half2*)&v0;
#pragma unroll
        for (int q = 0; q < 4; q++) {
            float2 f0 = __half22float2(p0[q]);
            acc[q * 2 + 0] += w0 * f0.x;
            acc[q * 2 + 1] += w0 * f0.y;
        }
    }

    float4 b0 = __ldg((const float4*)(bias + c8 * 8));
    float4 b1 = __ldg((const float4*)(bias + c8 * 8 + 4));
    acc[0] += b0.x; acc[1] += b0.y; acc[2] += b0.z; acc[3] += b0.w;
    acc[4] += b1.x; acc[5] += b1.y; acc[6] += b1.z; acc[7] += b1.w;
    if (RELU) {
#pragma unroll
        for (int q = 0; q < 8; q++) acc[q] = fmaxf(acc[q], 0.0f);
    }
    float* dst = g_agg + (size_t)node * 256 + c8 * 8;
    *(float4*)(dst + 0) = make_float4(acc[0], acc[1], acc[2], acc[3]);
    *(float4*)(dst + 4) = make_float4(acc[4], acc[5], acc[6], acc[7]);
}

// narrow (40-ch) aggregation for layer 3, h in fp16
__global__ void aggregate40_kernel(const float* __restrict__ bias, int n)
{
    const int node = blockIdx.x;
    const int c = threadIdx.x;
    if (node >= n || c >= OUTCH) return;
    const int beg = g_rowptr[node];
    const int end = g_rowptr[node + 1];
    const float di = g_dinv[node];
    float acc = __half2float(g_h16[(size_t)node * OUTCH + c]) * di * di;
    for (int e = beg; e < end; e++) {
        int   s = __ldg(&g_src_sorted[e]);
        float w = __ldg(&g_norm_sorted[e]);
        acc += w * __half2float(__ldg(&g_h16[(size_t)s * OUTCH + c]));
    }
    g_agg[(size_t)node * OUTCH + c] = acc + bias[c];
}

// ------------------------- log_softmax --------------------------------------

__global__ void logsoftmax_kernel(float* __restrict__ out, int n)
{
    int gtid = blockIdx.x * blockDim.x + threadIdx.x;
    int warp = gtid >> 5;
    int lane = gtid & 31;
    if (warp >= n) return;
    const float* v = g_agg + (size_t)warp * OUTCH;
    float x0 = v[lane];
    float x1 = (lane < OUTCH - 32) ? v[32 + lane] : -INFINITY;
    float m = fmaxf(x0, x1);
#pragma unroll
    for (int off = 16; off > 0; off >>= 1)
        m = fmaxf(m, __shfl_xor_sync(0xFFFFFFFF, m, off));
    float s = expf(x0 - m) + ((lane < OUTCH - 32) ? expf(x1 - m) : 0.0f);
#pragma unroll
    for (int off = 16; off > 0; off >>= 1)
        s += __shfl_xor_sync(0xFFFFFFFF, s, off);
    float lse = logf(s);
    float* o = out + (size_t)warp * OUTCH;
    o[lane] = x0 - m - lse;
    if (lane < OUTCH - 32) o[32 + lane] = x1 - m - lse;
}

// ------------------------- launch -------------------------

extern "C" void kernel_launch(void* const* d_in, const int* in_sizes, int n_in,
                              void* d_out, int out_size)
{
    const float* x  = (const float*)d_in[0];
    const int*   ei = (const int*)d_in[1];       // int32
    const float* W1 = (const float*)d_in[2];
    const float* b1 = (const float*)d_in[3];
    const float* W2 = (const float*)d_in[4];
    const float* b2 = (const float*)d_in[5];
    const float* W3 = (const float*)d_in[6];
    const float* b3 = (const float*)d_in[7];
    float* out = (float*)d_out;

    const int N = in_sizes[0] / CH;       // 100000
    const int E = in_sizes[1] / 2;        // 1600000
    const int NB = (N + SCAN_CHUNK - 1) / SCAN_CHUNK;

    // --- CSR build ---
    zero_cnt_kernel<<<(N + 255) / 256, 256>>>(N);
    hist_kernel<<<(E + 255) / 256, 256>>>(ei, E);
    scan_partial_kernel<<<NB, 256>>>(N);
    scan_blocks_kernel<<<1, 128>>>(NB);
    scan_emit_kernel<<<NB, 256>>>(N, E);
    scatter_kernel<<<(E + 255) / 256, 256>>>(ei, E);

    dim3 gemmGrid(CH / GBN, (N + GBM - 1) / GBM);   // (2, 782)
    const int aggBlocks = (N + 7) / 8;

    // --- layer 1 ---
    gemm_tf32_mma_kernel<false><<<gemmGrid, 256>>>(x, W1, N);
    aggregate256_kernel<true><<<aggBlocks, 256>>>(b1, N);
    // --- layer 2 ---
    gemm_tf32_mma_kernel<true><<<gemmGrid, 256>>>(nullptr, W2, N);
    aggregate256_kernel<true><<<aggBlocks, 256>>>(b2, N);
    // --- layer 3: fp32 GEMM (N=40) -> fp16 h, aggregate narrow, log_softmax
    {
        dim3 grid(1, (N + 127) / 128);
        sgemm_kernel<<<grid, 256>>>(W3, N, OUTCH, CH);
        aggregate40_kernel<<<N, 64>>>(b3, N);
        int blocks = (N * 32 + 255) / 256;
        logsoftmax_kernel<<<blocks, 256>>>(out, N);
    }
}

// round 7
// speedup vs baseline: 2.7160x; 1.0483x over previous
#include <cuda_runtime.h>
#include <cuda_fp16.h>
#include <math.h>
#include <stdint.h>

// ---------------------------------------------------------------------------
// GCN (3-layer) on 100k nodes / 1.6M edges.  edge_index arrives int32.
// R7: all intermediates fp16 (h AND agg) -> working set ~100MB, L2-resident.
// tf32 mma GEMMs (fp16 or fp32 A input via template); fused agg40+logsoftmax.
// ---------------------------------------------------------------------------

#define CH 256
#define OUTCH 40
#define N_NODES_MAX 100000
#define N_EDGES_MAX 1600000
#define SCAN_CHUNK 1024

__device__ __align__(16) __half g_h16[(size_t)N_NODES_MAX * CH];    // 50 MB
__device__ __align__(16) __half g_agg16[(size_t)N_NODES_MAX * CH];  // 50 MB
__device__ int   g_cnt[N_NODES_MAX];
__device__ int   g_rowptr[N_NODES_MAX + 1];
__device__ int   g_wptr[N_NODES_MAX];
__device__ float g_dinv[N_NODES_MAX];
__device__ int   g_src_sorted[N_EDGES_MAX];
__device__ float g_norm_sorted[N_EDGES_MAX];
__device__ int   g_blocksum[128];
__device__ int   g_blockoff[128];

// ------------------------- CSR build -------------------------

__global__ void zero_cnt_kernel(int n) {
    int i = blockIdx.x * blockDim.x + threadIdx.x;
    if (i < n) g_cnt[i] = 0;
}
__global__ void hist_kernel(const int* __restrict__ ei, int E) {
    int e = blockIdx.x * blockDim.x + threadIdx.x;
    if (e < E) atomicAdd(&g_cnt[ei[E + e]], 1);
}
__global__ void scan_partial_kernel(int n) {
    __shared__ int warpsum[8];
    int base = blockIdx.x * SCAN_CHUNK + threadIdx.x * 4;
    int s = 0;
#pragma unroll
    for (int j = 0; j < 4; j++) { int i = base + j; if (i < n) s += g_cnt[i]; }
    int lane = threadIdx.x & 31, w = threadIdx.x >> 5;
#pragma unroll
    for (int off = 16; off > 0; off >>= 1) s += __shfl_xor_sync(0xFFFFFFFF, s, off);
    if (lane == 0) warpsum[w] = s;
    __syncthreads();
    if (threadIdx.x == 0) {
        int t = 0;
#pragma unroll
        for (int k = 0; k < 8; k++) t += warpsum[k];
        g_blocksum[blockIdx.x] = t;
    }
}
__global__ void scan_blocks_kernel(int nb) {
    int t = threadIdx.x;
    int v = (t < nb) ? g_blocksum[t] : 0;
    int orig = v;
    int lane = t & 31, w = t >> 5;
#pragma unroll
    for (int off = 1; off < 32; off <<= 1) {
        int u = __shfl_up_sync(0xFFFFFFFF, v, off);
        if (lane >= off) v += u;
    }
    __shared__ int ws[4];
    if (lane == 31) ws[w] = v;
    __syncthreads();
    int add = 0;
    for (int k = 0; k < w; k++) add += ws[k];
    if (t < nb) g_blockoff[t] = v + add - orig;
}
__global__ void scan_emit_kernel(int n, int E) {
    __shared__ int warpincl[8];
    int base = blockIdx.x * SCAN_CHUNK + threadIdx.x * 4;
    int c[4];
    int s = 0;
#pragma unroll
    for (int j = 0; j < 4; j++) {
        int i = base + j;
        c[j] = (i < n) ? g_cnt[i] : 0;
        s += c[j];
    }
    int lane = threadIdx.x & 31, w = threadIdx.x >> 5;
    int v = s;
#pragma unroll
    for (int off = 1; off < 32; off <<= 1) {
        int u = __shfl_up_sync(0xFFFFFFFF, v, off);
        if (lane >= off) v += u;
    }
    if (lane == 31) warpincl[w] = v;
    __syncthreads();
    int add = 0;
    for (int k = 0; k < w; k++) add += warpincl[k];
    int run = g_blockoff[blockIdx.x] + add + v - s;
#pragma unroll
    for (int j = 0; j < 4; j++) {
        int i = base + j;
        if (i < n) {
            g_rowptr[i] = run;
            g_wptr[i]   = run;
            g_dinv[i]   = rsqrtf((float)c[j] + 1.0f);
            run += c[j];
        }
    }
    if (blockIdx.x == 0 && threadIdx.x == 0) g_rowptr[n] = E;
}
__global__ void scatter_kernel(const int* __restrict__ ei, int E) {
    int e = blockIdx.x * blockDim.x + threadIdx.x;
    if (e < E) {
        int s = ei[e];
        int d = ei[E + e];
        int pos = atomicAdd(&g_wptr[d], 1);
        g_src_sorted[pos]  = s;
        g_norm_sorted[pos] = g_dinv[s] * g_dinv[d];
    }
}

// ------------------- TF32 mma.sync GEMM: g_h16[M,256] = A[M,256] @ B[256,256]
// AKIND: 0 = fp32 global A (layer 1: x), 1 = fp16 g_agg16 (layers 2+).
// BM=128, BN=128, BK=16. 8 warps in 2(M)x4(N); warp tile = 64x32.

#define GBM 128
#define GBN 128
#define GBK 16
#define ASTRIDE 20
#define BSTRIDE 136

__device__ __forceinline__ uint32_t f2tf32(float f) {
    uint32_t u;
    asm("cvt.rna.tf32.f32 %0, %1;" : "=r"(u) : "f"(f));
    return u;
}

template <int AKIND>
__global__ __launch_bounds__(256, 2) void gemm_tf32_mma_kernel(
    const float* __restrict__ Aparam, const float* __restrict__ B, int M)
{
    __shared__ uint32_t As[2][GBM][ASTRIDE];   // [m][k]
    __shared__ uint32_t Bs[2][GBK][BSTRIDE];   // [k][n]

    const int tid  = threadIdx.x;
    const int wid  = tid >> 5;
    const int lane = tid & 31;
    const int grp  = lane >> 2;
    const int tig  = lane & 3;
    const int wm   = wid & 1;
    const int wn   = wid >> 1;
    const int m0   = blockIdx.y * GBM;
    const int n0   = blockIdx.x * GBN;

    float4 aReg[2];      // AKIND==0 path
    uint4  aH;           // AKIND==1 path (8 halves)
    float4 bReg[2];

    // fp16-A mapping: row = tid>>1 (0..127), half-group = (tid&1)*8
    const int hrow = tid >> 1;
    const int hc8  = (tid & 1) * 8;

    auto loadG = [&](int k0) {
        if (AKIND == 0) {
#pragma unroll
            for (int i = 0; i < 2; i++) {
                int idx = tid + i * 256;
                int row = idx >> 2, ac4 = idx & 3;
                int gm = m0 + row;
                aReg[i] = (gm < M)
                    ? __ldg((const float4*)(Aparam + (size_t)gm * 256 + k0 + ac4 * 4))
                    : make_float4(0.f, 0.f, 0.f, 0.f);
            }
        } else {
            int gm = m0 + hrow;
            aH = (gm < M)
                ? __ldg((const uint4*)(g_agg16 + (size_t)gm * 256 + k0 + hc8))
                : make_uint4(0u, 0u, 0u, 0u);
        }
#pragma unroll
        for (int i = 0; i < 2; i++) {
            int idx = tid + i * 256;
            int bk = idx >> 5, bc4 = idx & 31;
            bReg[i] = __ldg((const float4*)(B + (size_t)(k0 + bk) * 256 + n0 + bc4 * 4));
        }
    };
    auto storeS = [&](int buf) {
        if (AKIND == 0) {
#pragma unroll
            for (int i = 0; i < 2; i++) {
                int idx = tid + i * 256;
                int row = idx >> 2, ac4 = idx & 3;
                uint4 av = make_uint4(f2tf32(aReg[i].x), f2tf32(aReg[i].y),
                                      f2tf32(aReg[i].z), f2tf32(aReg[i].w));
                *(uint4*)&As[buf][row][ac4 * 4] = av;
            }
        } else {
            const __half2* hp = (const __half2*)&aH;
            uint32_t t[8];
#pragma unroll
            for (int q = 0; q < 4; q++) {
                float2 f = __half22float2(hp[q]);
                t[q * 2 + 0] = f2tf32(f.x);
                t[q * 2 + 1] = f2tf32(f.y);
            }
            *(uint4*)&As[buf][hrow][hc8 + 0] = make_uint4(t[0], t[1], t[2], t[3]);
            *(uint4*)&As[buf][hrow][hc8 + 4] = make_uint4(t[4], t[5], t[6], t[7]);
        }
#pragma unroll
        for (int i = 0; i < 2; i++) {
            int idx = tid + i * 256;
            int bk = idx >> 5, bc4 = idx & 31;
            uint4 bv = make_uint4(f2tf32(bReg[i].x), f2tf32(bReg[i].y),
                                  f2tf32(bReg[i].z), f2tf32(bReg[i].w));
            *(uint4*)&Bs[buf][bk][bc4 * 4] = bv;
        }
    };

    float acc[4][4][4];
#pragma unroll
    for (int mt = 0; mt < 4; mt++)
#pragma unroll
        for (int nt = 0; nt < 4; nt++)
#pragma unroll
            for (int r = 0; r < 4; r++) acc[mt][nt][r] = 0.0f;

    loadG(0);
    storeS(0);
    __syncthreads();

    const int NT = 256 / GBK;
    for (int kt = 0; kt < NT; kt++) {
        const int cur = kt & 1;
        if (kt + 1 < NT) loadG((kt + 1) * GBK);

#pragma unroll
        for (int ks = 0; ks < 2; ks++) {
            const int kk = ks * 8 + tig;
            uint32_t af[4][4], bf[4][2];
#pragma unroll
            for (int mt = 0; mt < 4; mt++) {
                int mr = wm * 64 + mt * 16 + grp;
                af[mt][0] = As[cur][mr][kk];
                af[mt][1] = As[cur][mr + 8][kk];
                af[mt][2] = As[cur][mr][kk + 4];
                af[mt][3] = As[cur][mr + 8][kk + 4];
            }
#pragma unroll
            for (int nt = 0; nt < 4; nt++) {
                int nc = wn * 32 + nt * 8 + grp;
                bf[nt][0] = Bs[cur][kk][nc];
                bf[nt][1] = Bs[cur][kk + 4][nc];
            }
#pragma unroll
            for (int mt = 0; mt < 4; mt++)
#pragma unroll
                for (int nt = 0; nt < 4; nt++) {
                    asm volatile(
                        "mma.sync.aligned.m16n8k8.row.col.f32.tf32.tf32.f32 "
                        "{%0,%1,%2,%3}, {%4,%5,%6,%7}, {%8,%9}, {%0,%1,%2,%3};"
                        : "+f"(acc[mt][nt][0]), "+f"(acc[mt][nt][1]),
                          "+f"(acc[mt][nt][2]), "+f"(acc[mt][nt][3])
                        : "r"(af[mt][0]), "r"(af[mt][1]), "r"(af[mt][2]), "r"(af[mt][3]),
                          "r"(bf[nt][0]), "r"(bf[nt][1]));
                }
        }
        if (kt + 1 < NT) storeS(cur ^ 1);
        __syncthreads();
    }

    // epilogue: convert to fp16, store half2
#pragma unroll
    for (int mt = 0; mt < 4; mt++) {
        int gm = m0 + wm * 64 + mt * 16 + grp;
#pragma unroll
        for (int nt = 0; nt < 4; nt++) {
            int gn = n0 + wn * 32 + nt * 8 + tig * 2;
            if (gm < M) {
                __half2 v = __floats2half2_rn(acc[mt][nt][0], acc[mt][nt][1]);
                *(__half2*)(g_h16 + (size_t)gm * 256 + gn) = v;
            }
            if (gm + 8 < M) {
                __half2 v = __floats2half2_rn(acc[mt][nt][2], acc[mt][nt][3]);
                *(__half2*)(g_h16 + (size_t)(gm + 8) * 256 + gn) = v;
            }
        }
    }
}

// ---------- layer-3 SGEMM (N=40, K=256): A = g_agg16 (fp16), C = g_h16 ------

__global__ __launch_bounds__(256) void sgemm40_kernel(
    const float* __restrict__ B, int M, int N, int K)
{
    constexpr int BM = 128, BN = 128, BK = 16;
    __shared__ float As[2][BK][BM];
    __shared__ float Bs[2][BK][BN];

    const int tid = threadIdx.x;
    const int tx  = tid & 15;
    const int ty  = tid >> 4;
    const int m0  = blockIdx.y * BM;
    const int n0  = blockIdx.x * BN;

    const int ar = tid >> 2;
    const int ak = (tid & 3) * 4;
    const int br = tid >> 5;
    const int bc = (tid & 31) * 4;

    float4 aReg[2], bReg[2];
    auto loadTile = [&](int k0) {
#pragma unroll
        for (int p = 0; p < 2; p++) {
            int gm = m0 + ar + p * 64;
            if (gm < M) {
                uint2 hv = __ldg((const uint2*)(g_agg16 + (size_t)gm * K + k0 + ak));
                const __half2* hp = (const __half2*)&hv;
                float2 f0 = __half22float2(hp[0]);
                float2 f1 = __half22float2(hp[1]);
                aReg[p] = make_float4(f0.x, f0.y, f1.x, f1.y);
            } else {
                aReg[p] = make_float4(0.f, 0.f, 0.f, 0.f);
            }
            int gk = k0 + br + p * 8;
            int gn = n0 + bc;
            if (gn + 3 < N) {
                bReg[p] = *(const float4*)(B + (size_t)gk * N + gn);
            } else {
                float t0 = (gn + 0 < N) ? B[(size_t)gk * N + gn + 0] : 0.f;
                float t1 = (gn + 1 < N) ? B[(size_t)gk * N + gn + 1] : 0.f;
                float t2 = (gn + 2 < N) ? B[(size_t)gk * N + gn + 2] : 0.f;
                float t3 = (gn + 3 < N) ? B[(size_t)gk * N + gn + 3] : 0.f;
                bReg[p] = make_float4(t0, t1, t2, t3);
            }
        }
    };
    auto storeTile = [&](int buf) {
#pragma unroll
        for (int p = 0; p < 2; p++) {
            int r = ar + p * 64;
            As[buf][ak + 0][r] = aReg[p].x;
            As[buf][ak + 1][r] = aReg[p].y;
            As[buf][ak + 2][r] = aReg[p].z;
            As[buf][ak + 3][r] = aReg[p].w;
            *(float4*)&Bs[buf][br + p * 8][bc] = bReg[p];
        }
    };

    float acc[8][8];
#pragma unroll
    for (int i = 0; i < 8; i++)
#pragma unroll
        for (int j = 0; j < 8; j++) acc[i][j] = 0.0f;

    loadTile(0);
    storeTile(0);
    __syncthreads();

    const int NTt = K / BK;
    for (int kt = 0; kt < NTt; kt++) {
        int cur = kt & 1;
        if (kt + 1 < NTt) loadTile((kt + 1) * BK);
#pragma unroll
        for (int k = 0; k < BK; k++) {
            float a[8], b[8];
            *(float4*)&a[0] = *(const float4*)&As[cur][k][ty * 8];
            *(float4*)&a[4] = *(const float4*)&As[cur][k][ty * 8 + 4];
            *(float4*)&b[0] = *(const float4*)&Bs[cur][k][tx * 8];
            *(float4*)&b[4] = *(const float4*)&Bs[cur][k][tx * 8 + 4];
#pragma unroll
            for (int i = 0; i < 8; i++)
#pragma unroll
                for (int j = 0; j < 8; j++) acc[i][j] += a[i] * b[j];
        }
        if (kt + 1 < NTt) storeTile(cur ^ 1);
        __syncthreads();
    }

#pragma unroll
    for (int i = 0; i < 8; i++) {
        int gm = m0 + ty * 8 + i;
        if (gm >= M) continue;
#pragma unroll
        for (int j = 0; j < 8; j++) {
            int gn = n0 + tx * 8 + j;
            if (gn < N) g_h16[(size_t)gm * N + gn] = __float2half_rn(acc[i][j]);
        }
    }
}

// ------------------- Aggregation 256-ch: h16 gather -> agg16 ----------------
// 8 nodes/block, 32 threads/node; thread gathers uint4 = 8 halves (16B).
template <bool RELU>
__global__ __launch_bounds__(256) void aggregate256_kernel(
    const float* __restrict__ bias, int n)
{
    const int node = blockIdx.x * 8 + (threadIdx.x >> 5);
    const int c8   = threadIdx.x & 31;
    if (node >= n) return;
    const uint4* h = (const uint4*)g_h16;
    const int beg = g_rowptr[node];
    const int end = g_rowptr[node + 1];
    const float di = g_dinv[node];
    const float dii = di * di;

    float acc[8];
    {
        uint4 v = h[(size_t)node * 32 + c8];
        const __half2* hp = (const __half2*)&v;
#pragma unroll
        for (int q = 0; q < 4; q++) {
            float2 f = __half22float2(hp[q]);
            acc[q * 2 + 0] = f.x * dii;
            acc[q * 2 + 1] = f.y * dii;
        }
    }

    int e = beg;
    for (; e + 2 <= end; e += 2) {
        int   s0 = __ldg(&g_src_sorted[e]);
        int   s1 = __ldg(&g_src_sorted[e + 1]);
        float w0 = __ldg(&g_norm_sorted[e]);
        float w1 = __ldg(&g_norm_sorted[e + 1]);
        uint4 v0 = __ldg(&h[(size_t)s0 * 32 + c8]);
        uint4 v1 = __ldg(&h[(size_t)s1 * 32 + c8]);
        const __half2* p0 = (const __half2*)&v0;
        const __half2* p1 = (const __half2*)&v1;
#pragma unroll
        for (int q = 0; q < 4; q++) {
            float2 f0 = __half22float2(p0[q]);
            float2 f1 = __half22float2(p1[q]);
            acc[q * 2 + 0] += w0 * f0.x + w1 * f1.x;
            acc[q * 2 + 1] += w0 * f0.y + w1 * f1.y;
        }
    }
    if (e < end) {
        int   s0 = __ldg(&g_src_sorted[e]);
        float w0 = __ldg(&g_norm_sorted[e]);
        uint4 v0 = __ldg(&h[(size_t)s0 * 32 + c8]);
        const __half2* p0 = (const __half2*)&v0;
#pragma unroll
        for (int q = 0; q < 4; q++) {
            float2 f0 = __half22float2(p0[q]);
            acc[q * 2 + 0] += w0 * f0.x;
            acc[q * 2 + 1] += w0 * f0.y;
        }
    }

    float4 b0 = __ldg((const float4*)(bias + c8 * 8));
    float4 b1 = __ldg((const float4*)(bias + c8 * 8 + 4));
    acc[0] += b0.x; acc[1] += b0.y; acc[2] += b0.z; acc[3] += b0.w;
    acc[4] += b1.x; acc[5] += b1.y; acc[6] += b1.z; acc[7] += b1.w;
    if (RELU) {
#pragma unroll
        for (int q = 0; q < 8; q++) acc[q] = fmaxf(acc[q], 0.0f);
    }
    // pack to fp16 and store uint4 (8 halves)
    uint4 ov;
    __half2* op = (__half2*)&ov;
    op[0] = __floats2half2_rn(acc[0], acc[1]);
    op[1] = __floats2half2_rn(acc[2], acc[3]);
    op[2] = __floats2half2_rn(acc[4], acc[5]);
    op[3] = __floats2half2_rn(acc[6], acc[7]);
    ((uint4*)g_agg16)[(size_t)node * 32 + c8] = ov;
}

// ---------- fused layer-3 aggregation (40 ch) + log_softmax -----------------
// one block of 64 threads per node

__global__ __launch_bounds__(64) void agg40_softmax_kernel(
    const float* __restrict__ bias, float* __restrict__ out, int n)
{
    __shared__ float sv[OUTCH];
    const int node = blockIdx.x;
    const int c = threadIdx.x;
    if (c < OUTCH) {
        const int beg = g_rowptr[node];
        const int end = g_rowptr[node + 1];
        const float di = g_dinv[node];
        float acc = __half2float(g_h16[(size_t)node * OUTCH + c]) * di * di;
        for (int e = beg; e < end; e++) {
            int   s = __ldg(&g_src_sorted[e]);
            float w = __ldg(&g_norm_sorted[e]);
            acc += w * __half2float(__ldg(&g_h16[(size_t)s * OUTCH + c]));
        }
        sv[c] = acc + bias[c];
    }
    __syncthreads();
    if (threadIdx.x < 32) {
        int lane = threadIdx.x;
        float x0 = sv[lane];
        float x1 = (lane < OUTCH - 32) ? sv[32 + lane] : -INFINITY;
        float m = fmaxf(x0, x1);
#pragma unroll
        for (int off = 16; off > 0; off >>= 1)
            m = fmaxf(m, __shfl_xor_sync(0xFFFFFFFF, m, off));
        float s = expf(x0 - m) + ((lane < OUTCH - 32) ? expf(x1 - m) : 0.0f);
#pragma unroll
        for (int off = 16; off > 0; off >>= 1)
            s += __shfl_xor_sync(0xFFFFFFFF, s, off);
        float lse = logf(s);
        float* o = out + (size_t)node * OUTCH;
        o[lane] = x0 - m - lse;
        if (lane < OUTCH - 32) o[32 + lane] = x1 - m - lse;
    }
}

// ------------------------- launch -------------------------

extern "C" void kernel_launch(void* const* d_in, const int* in_sizes, int n_in,
                              void* d_out, int out_size)
{
    const float* x  = (const float*)d_in[0];
    const int*   ei = (const int*)d_in[1];       // int32
    const float* W1 = (const float*)d_in[2];
    const float* b1 = (const float*)d_in[3];
    const float* W2 = (const float*)d_in[4];
    const float* b2 = (const float*)d_in[5];
    const float* W3 = (const float*)d_in[6];
    const float* b3 = (const float*)d_in[7];
    float* out = (float*)d_out;

    const int N = in_sizes[0] / CH;       // 100000
    const int E = in_sizes[1] / 2;        // 1600000
    const int NB = (N + SCAN_CHUNK - 1) / SCAN_CHUNK;

    // --- CSR build ---
    zero_cnt_kernel<<<(N + 255) / 256, 256>>>(N);
    hist_kernel<<<(E + 255) / 256, 256>>>(ei, E);
    scan_partial_kernel<<<NB, 256>>>(N);
    scan_blocks_kernel<<<1, 128>>>(NB);
    scan_emit_kernel<<<NB, 256>>>(N, E);
    scatter_kernel<<<(E + 255) / 256, 256>>>(ei, E);

    dim3 gemmGrid(CH / GBN, (N + GBM - 1) / GBM);   // (2, 782)
    const int aggBlocks = (N + 7) / 8;

    // --- layer 1 (fp32 A = x) ---
    gemm_tf32_mma_kernel<0><<<gemmGrid, 256>>>(x, W1, N);
    aggregate256_kernel<true><<<aggBlocks, 256>>>(b1, N);
    // --- layer 2 (fp16 A = g_agg16) ---
    gemm_tf32_mma_kernel<1><<<gemmGrid, 256>>>(nullptr, W2, N);
    aggregate256_kernel<true><<<aggBlocks, 256>>>(b2, N);
    // --- layer 3: SIMT GEMM (N=40, fp16 A) -> fused agg+softmax ---
    {
        dim3 grid(1, (N + 127) / 128);
        sgemm40_kernel<<<grid, 256>>>(W3, N, OUTCH, CH);
        agg40_softmax_kernel<<<N, 64>>>(b3, out, N);
    }
}

// round 8
// speedup vs baseline: 3.7941x; 1.3970x over previous
#include <cuda_runtime.h>
#include <cuda_fp16.h>
#include <math.h>
#include <stdint.h>

// ---------------------------------------------------------------------------
// GCN (3-layer) on 100k nodes / 1.6M edges.  edge_index arrives int32.
// R8: all GEMMs on fp16 m16n8k16 mma.sync (fp32 accum). x / W converted to
// fp16 once per call (W stored transposed [n][k]). Aggregation unroll x4.
// ---------------------------------------------------------------------------

#define CH 256
#define OUTCH 40
#define N_NODES_MAX 100000
#define N_EDGES_MAX 1600000
#define SCAN_CHUNK 1024

__device__ __align__(16) __half g_x16[(size_t)N_NODES_MAX * CH];    // 50 MB
__device__ __align__(16) __half g_h16[(size_t)N_NODES_MAX * CH];    // 50 MB
__device__ __align__(16) __half g_agg16[(size_t)N_NODES_MAX * CH];  // 50 MB
__device__ __align__(16) __half g_w1t[CH * CH];      // [n][k] transposed
__device__ __align__(16) __half g_w2t[CH * CH];
__device__ __align__(16) __half g_w3t[64 * CH];      // padded to 64 rows
__device__ int   g_cnt[N_NODES_MAX];
__device__ int   g_rowptr[N_NODES_MAX + 1];
__device__ int   g_wptr[N_NODES_MAX];
__device__ float g_dinv[N_NODES_MAX];
__device__ int   g_src_sorted[N_EDGES_MAX];
__device__ float g_norm_sorted[N_EDGES_MAX];
__device__ int   g_blocksum[128];
__device__ int   g_blockoff[128];

// ------------------------- CSR build -------------------------

__global__ void zero_cnt_kernel(int n) {
    int i = blockIdx.x * blockDim.x + threadIdx.x;
    if (i < n) g_cnt[i] = 0;
}
__global__ void hist_kernel(const int* __restrict__ ei, int E) {
    int e = blockIdx.x * blockDim.x + threadIdx.x;
    if (e < E) atomicAdd(&g_cnt[ei[E + e]], 1);
}
__global__ void scan_partial_kernel(int n) {
    __shared__ int warpsum[8];
    int base = blockIdx.x * SCAN_CHUNK + threadIdx.x * 4;
    int s = 0;
#pragma unroll
    for (int j = 0; j < 4; j++) { int i = base + j; if (i < n) s += g_cnt[i]; }
    int lane = threadIdx.x & 31, w = threadIdx.x >> 5;
#pragma unroll
    for (int off = 16; off > 0; off >>= 1) s += __shfl_xor_sync(0xFFFFFFFF, s, off);
    if (lane == 0) warpsum[w] = s;
    __syncthreads();
    if (threadIdx.x == 0) {
        int t = 0;
#pragma unroll
        for (int k = 0; k < 8; k++) t += warpsum[k];
        g_blocksum[blockIdx.x] = t;
    }
}
__global__ void scan_blocks_kernel(int nb) {
    int t = threadIdx.x;
    int v = (t < nb) ? g_blocksum[t] : 0;
    int orig = v;
    int lane = t & 31, w = t >> 5;
#pragma unroll
    for (int off = 1; off < 32; off <<= 1) {
        int u = __shfl_up_sync(0xFFFFFFFF, v, off);
        if (lane >= off) v += u;
    }
    __shared__ int ws[4];
    if (lane == 31) ws[w] = v;
    __syncthreads();
    int add = 0;
    for (int k = 0; k < w; k++) add += ws[k];
    if (t < nb) g_blockoff[t] = v + add - orig;
}
__global__ void scan_emit_kernel(int n, int E) {
    __shared__ int warpincl[8];
    int base = blockIdx.x * SCAN_CHUNK + threadIdx.x * 4;
    int c[4];
    int s = 0;
#pragma unroll
    for (int j = 0; j < 4; j++) {
        int i = base + j;
        c[j] = (i < n) ? g_cnt[i] : 0;
        s += c[j];
    }
    int lane = threadIdx.x & 31, w = threadIdx.x >> 5;
    int v = s;
#pragma unroll
    for (int off = 1; off < 32; off <<= 1) {
        int u = __shfl_up_sync(0xFFFFFFFF, v, off);
        if (lane >= off) v += u;
    }
    if (lane == 31) warpincl[w] = v;
    __syncthreads();
    int add = 0;
    for (int k = 0; k < w; k++) add += warpincl[k];
    int run = g_blockoff[blockIdx.x] + add + v - s;
#pragma unroll
    for (int j = 0; j < 4; j++) {
        int i = base + j;
        if (i < n) {
            g_rowptr[i] = run;
            g_wptr[i]   = run;
            g_dinv[i]   = rsqrtf((float)c[j] + 1.0f);
            run += c[j];
        }
    }
    if (blockIdx.x == 0 && threadIdx.x == 0) g_rowptr[n] = E;
}
__global__ void scatter_kernel(const int* __restrict__ ei, int E) {
    int e = blockIdx.x * blockDim.x + threadIdx.x;
    if (e < E) {
        int s = ei[e];
        int d = ei[E + e];
        int pos = atomicAdd(&g_wptr[d], 1);
        g_src_sorted[pos]  = s;
        g_norm_sorted[pos] = g_dinv[s] * g_dinv[d];
    }
}

// ------------------------- fp16 conversions -------------------------

__global__ void convert_x_kernel(const float* __restrict__ x, int total8) {
    int i = blockIdx.x * blockDim.x + threadIdx.x;
    if (i < total8) {
        float4 f0 = __ldg((const float4*)(x + (size_t)i * 8));
        float4 f1 = __ldg((const float4*)(x + (size_t)i * 8 + 4));
        uint4 v;
        __half2* p = (__half2*)&v;
        p[0] = __floats2half2_rn(f0.x, f0.y);
        p[1] = __floats2half2_rn(f0.z, f0.w);
        p[2] = __floats2half2_rn(f1.x, f1.y);
        p[3] = __floats2half2_rn(f1.z, f1.w);
        ((uint4*)g_x16)[i] = v;
    }
}

// W1,W2 [k][n] fp32 -> [n][k] fp16; W3 [k][40] -> [64][k] fp16 (zero-padded)
__global__ void convert_w_kernel(const float* __restrict__ W1,
                                 const float* __restrict__ W2,
                                 const float* __restrict__ W3) {
    int n = blockIdx.x;      // 0..255
    int k = threadIdx.x;     // 0..255
    g_w1t[n * 256 + k] = __float2half_rn(__ldg(&W1[k * 256 + n]));
    g_w2t[n * 256 + k] = __float2half_rn(__ldg(&W2[k * 256 + n]));
    if (n < 64)
        g_w3t[n * 256 + k] = __float2half_rn(n < OUTCH ? __ldg(&W3[k * OUTCH + n]) : 0.f);
}

// ------------------- fp16 mma GEMM: C[M,*] = A16[M,256] @ W^T ---------------
// BM=128, BN=128 or 64, BK=16. 8 warps 2(M)x4(N); warp tile 64 x BN/4.
// smem [row][24 halves] (stride 24 => conflict-free half2 fragment loads).
// ASEL: 0 = g_x16, 1 = g_agg16.  WSEL: 0/1/2 = g_w1t/g_w2t/g_w3t.

#define HSTR 24

template <int BN, int ASEL, int WSEL>
__global__ __launch_bounds__(256, 2) void gemm_h16_kernel(
    int M, int NOUT, int OS)
{
    const __half* Aptr = (ASEL == 0) ? g_x16 : g_agg16;
    const __half* Bt   = (WSEL == 0) ? g_w1t : (WSEL == 1) ? g_w2t : g_w3t;
    constexpr int NTN = BN / 32;          // n-tiles per warp

    __shared__ __half As[2][128][HSTR];
    __shared__ __half Bs[2][BN][HSTR];

    const int tid  = threadIdx.x;
    const int wid  = tid >> 5;
    const int lane = tid & 31;
    const int grp  = lane >> 2;
    const int tig  = lane & 3;
    const int wm   = wid & 1;
    const int wn   = wid >> 1;
    const int m0   = blockIdx.y * 128;
    const int n0   = blockIdx.x * BN;

    const int row = tid >> 1;
    const int kc  = tid & 1;

    uint4 aG, bG;
    auto loadG = [&](int k0) {
        int gm = m0 + row;
        aG = (gm < M) ? __ldg((const uint4*)(Aptr + (size_t)gm * 256 + k0 + kc * 8))
                      : make_uint4(0u, 0u, 0u, 0u);
        if (BN == 128) {
            bG = __ldg((const uint4*)(Bt + (size_t)(n0 + row) * 256 + k0 + kc * 8));
        } else {
            if (tid < BN * 2)
                bG = __ldg((const uint4*)(Bt + (size_t)(n0 + row) * 256 + k0 + kc * 8));
        }
    };
    auto storeS = [&](int buf) {
        *(uint4*)&As[buf][row][kc * 8] = aG;
        if (BN == 128) {
            *(uint4*)&Bs[buf][row][kc * 8] = bG;
        } else {
            if (tid < BN * 2) *(uint4*)&Bs[buf][row][kc * 8] = bG;
        }
    };

    float acc[4][NTN][4];
#pragma unroll
    for (int mt = 0; mt < 4; mt++)
#pragma unroll
        for (int nt = 0; nt < NTN; nt++)
#pragma unroll
            for (int r = 0; r < 4; r++) acc[mt][nt][r] = 0.0f;

    loadG(0);
    storeS(0);
    __syncthreads();

    const int NT = 256 / 16;
    for (int kt = 0; kt < NT; kt++) {
        const int cur = kt & 1;
        if (kt + 1 < NT) loadG((kt + 1) * 16);

        uint32_t af[4][4], bf[NTN][2];
#pragma unroll
        for (int mt = 0; mt < 4; mt++) {
            const __half* pa = &As[cur][wm * 64 + mt * 16 + grp][tig * 2];
            af[mt][0] = *(const uint32_t*)pa;
            af[mt][1] = *(const uint32_t*)(pa + 8 * HSTR);
            af[mt][2] = *(const uint32_t*)(pa + 8);
            af[mt][3] = *(const uint32_t*)(pa + 8 * HSTR + 8);
        }
#pragma unroll
        for (int nt = 0; nt < NTN; nt++) {
            const __half* pb = &Bs[cur][wn * (BN / 4) + nt * 8 + grp][tig * 2];
            bf[nt][0] = *(const uint32_t*)pb;
            bf[nt][1] = *(const uint32_t*)(pb + 8);
        }
#pragma unroll
        for (int mt = 0; mt < 4; mt++)
#pragma unroll
            for (int nt = 0; nt < NTN; nt++) {
                asm volatile(
                    "mma.sync.aligned.m16n8k16.row.col.f32.f16.f16.f32 "
                    "{%0,%1,%2,%3}, {%4,%5,%6,%7}, {%8,%9}, {%0,%1,%2,%3};"
                    : "+f"(acc[mt][nt][0]), "+f"(acc[mt][nt][1]),
                      "+f"(acc[mt][nt][2]), "+f"(acc[mt][nt][3])
                    : "r"(af[mt][0]), "r"(af[mt][1]), "r"(af[mt][2]), "r"(af[mt][3]),
                      "r"(bf[nt][0]), "r"(bf[nt][1]));
            }
        if (kt + 1 < NT) storeS(cur ^ 1);
        __syncthreads();
    }

    // epilogue -> g_h16 with row stride OS, guard col < NOUT
#pragma unroll
    for (int mt = 0; mt < 4; mt++) {
        int gm = m0 + wm * 64 + mt * 16 + grp;
#pragma unroll
        for (int nt = 0; nt < NTN; nt++) {
            int gn = n0 + wn * (BN / 4) + nt * 8 + tig * 2;
            if (gn < NOUT) {
                if (gm < M)
                    *(__half2*)(g_h16 + (size_t)gm * OS + gn) =
                        __floats2half2_rn(acc[mt][nt][0], acc[mt][nt][1]);
                if (gm + 8 < M)
                    *(__half2*)(g_h16 + (size_t)(gm + 8) * OS + gn) =
                        __floats2half2_rn(acc[mt][nt][2], acc[mt][nt][3]);
            }
        }
    }
}

// ------------------- Aggregation 256-ch: h16 gather -> agg16 ----------------
// 8 nodes/block, 32 threads/node; thread gathers uint4 = 8 halves; unroll 4.
template <bool RELU>
__global__ __launch_bounds__(256) void aggregate256_kernel(
    const float* __restrict__ bias, int n)
{
    const int node = blockIdx.x * 8 + (threadIdx.x >> 5);
    const int c8   = threadIdx.x & 31;
    if (node >= n) return;
    const uint4* h = (const uint4*)g_h16;
    const int beg = g_rowptr[node];
    const int end = g_rowptr[node + 1];
    const float di = g_dinv[node];
    const float dii = di * di;

    float acc[8];
    {
        uint4 v = h[(size_t)node * 32 + c8];
        const __half2* hp = (const __half2*)&v;
#pragma unroll
        for (int q = 0; q < 4; q++) {
            float2 f = __half22float2(hp[q]);
            acc[q * 2 + 0] = f.x * dii;
            acc[q * 2 + 1] = f.y * dii;
        }
    }

    int e = beg;
    for (; e + 4 <= end; e += 4) {
        int   s0 = __ldg(&g_src_sorted[e + 0]);
        int   s1 = __ldg(&g_src_sorted[e + 1]);
        int   s2 = __ldg(&g_src_sorted[e + 2]);
        int   s3 = __ldg(&g_src_sorted[e + 3]);
        float w0 = __ldg(&g_norm_sorted[e + 0]);
        float w1 = __ldg(&g_norm_sorted[e + 1]);
        float w2 = __ldg(&g_norm_sorted[e + 2]);
        float w3 = __ldg(&g_norm_sorted[e + 3]);
        uint4 v0 = __ldg(&h[(size_t)s0 * 32 + c8]);
        uint4 v1 = __ldg(&h[(size_t)s1 * 32 + c8]);
        uint4 v2 = __ldg(&h[(size_t)s2 * 32 + c8]);
        uint4 v3 = __ldg(&h[(size_t)s3 * 32 + c8]);
        const __half2* p0 = (const __half2*)&v0;
        const __half2* p1 = (const __half2*)&v1;
        const __half2* p2 = (const __half2*)&v2;
        const __half2* p3 = (const __half2*)&v3;
#pragma unroll
        for (int q = 0; q < 4; q++) {
            float2 f0 = __half22float2(p0[q]);
            float2 f1 = __half22float2(p1[q]);
            float2 f2 = __half22float2(p2[q]);
            float2 f3 = __half22float2(p3[q]);
            acc[q * 2 + 0] += w0 * f0.x + w1 * f1.x + w2 * f2.x + w3 * f3.x;
            acc[q * 2 + 1] += w0 * f0.y + w1 * f1.y + w2 * f2.y + w3 * f3.y;
        }
    }
    for (; e < end; e++) {
        int   s0 = __ldg(&g_src_sorted[e]);
        float w0 = __ldg(&g_norm_sorted[e]);
        uint4 v0 = __ldg(&h[(size_t)s0 * 32 + c8]);
        const __half2* p0 = (const __half2*)&v0;
#pragma unroll
        for (int q = 0; q < 4; q++) {
            float2 f0 = __half22float2(p0[q]);
            acc[q * 2 + 0] += w0 * f0.x;
            acc[q * 2 + 1] += w0 * f0.y;
        }
    }

    float4 b0 = __ldg((const float4*)(bias + c8 * 8));
    float4 b1 = __ldg((const float4*)(bias + c8 * 8 + 4));
    acc[0] += b0.x; acc[1] += b0.y; acc[2] += b0.z; acc[3] += b0.w;
    acc[4] += b1.x; acc[5] += b1.y; acc[6] += b1.z; acc[7] += b1.w;
    if (RELU) {
#pragma unroll
        for (int q = 0; q < 8; q++) acc[q] = fmaxf(acc[q], 0.0f);
    }
    uint4 ov;
    __half2* op = (__half2*)&ov;
    op[0] = __floats2half2_rn(acc[0], acc[1]);
    op[1] = __floats2half2_rn(acc[2], acc[3]);
    op[2] = __floats2half2_rn(acc[4], acc[5]);
    op[3] = __floats2half2_rn(acc[6], acc[7]);
    ((uint4*)g_agg16)[(size_t)node * 32 + c8] = ov;
}

// ---------- fused layer-3 aggregation (40 ch) + log_softmax -----------------

__global__ __launch_bounds__(64) void agg40_softmax_kernel(
    const float* __restrict__ bias, float* __restrict__ out, int n)
{
    __shared__ float sv[OUTCH];
    const int node = blockIdx.x;
    const int c = threadIdx.x;
    if (c < OUTCH) {
        const int beg = g_rowptr[node];
        const int end = g_rowptr[node + 1];
        const float di = g_dinv[node];
        float acc = __half2float(g_h16[(size_t)node * OUTCH + c]) * di * di;
        for (int e = beg; e < end; e++) {
            int   s = __ldg(&g_src_sorted[e]);
            float w = __ldg(&g_norm_sorted[e]);
            acc += w * __half2float(__ldg(&g_h16[(size_t)s * OUTCH + c]));
        }
        sv[c] = acc + bias[c];
    }
    __syncthreads();
    if (threadIdx.x < 32) {
        int lane = threadIdx.x;
        float x0 = sv[lane];
        float x1 = (lane < OUTCH - 32) ? sv[32 + lane] : -INFINITY;
        float m = fmaxf(x0, x1);
#pragma unroll
        for (int off = 16; off > 0; off >>= 1)
            m = fmaxf(m, __shfl_xor_sync(0xFFFFFFFF, m, off));
        float s = expf(x0 - m) + ((lane < OUTCH - 32) ? expf(x1 - m) : 0.0f);
#pragma unroll
        for (int off = 16; off > 0; off >>= 1)
            s += __shfl_xor_sync(0xFFFFFFFF, s, off);
        float lse = logf(s);
        float* o = out + (size_t)node * OUTCH;
        o[lane] = x0 - m - lse;
        if (lane < OUTCH - 32) o[32 + lane] = x1 - m - lse;
    }
}

// ------------------------- launch -------------------------

extern "C" void kernel_launch(void* const* d_in, const int* in_sizes, int n_in,
                              void* d_out, int out_size)
{
    const float* x  = (const float*)d_in[0];
    const int*   ei = (const int*)d_in[1];       // int32
    const float* W1 = (const float*)d_in[2];
    const float* b1 = (const float*)d_in[3];
    const float* W2 = (const float*)d_in[4];
    const float* b2 = (const float*)d_in[5];
    const float* W3 = (const float*)d_in[6];
    const float* b3 = (const float*)d_in[7];
    float* out = (float*)d_out;

    const int N = in_sizes[0] / CH;       // 100000
    const int E = in_sizes[1] / 2;        // 1600000
    const int NB = (N + SCAN_CHUNK - 1) / SCAN_CHUNK;

    // --- CSR build + fp16 conversions ---
    zero_cnt_kernel<<<(N + 255) / 256, 256>>>(N);
    hist_kernel<<<(E + 255) / 256, 256>>>(ei, E);
    scan_partial_kernel<<<NB, 256>>>(N);
    scan_blocks_kernel<<<1, 128>>>(NB);
    scan_emit_kernel<<<NB, 256>>>(N, E);
    scatter_kernel<<<(E + 255) / 256, 256>>>(ei, E);

    const int total8 = N * CH / 8;
    convert_x_kernel<<<(total8 + 255) / 256, 256>>>(x, total8);
    convert_w_kernel<<<256, 256>>>(W1, W2, W3);

    const int mBlocks  = (N + 127) / 128;          // 782
    const int aggBlocks = (N + 7) / 8;

    // --- layer 1 ---
    {
        dim3 grid(2, mBlocks);
        gemm_h16_kernel<128, 0, 0><<<grid, 256>>>(N, CH, CH);
        aggregate256_kernel<true><<<aggBlocks, 256>>>(b1, N);
    }
    // --- layer 2 ---
    {
        dim3 grid(2, mBlocks);
        gemm_h16_kernel<128, 1, 1><<<grid, 256>>>(N, CH, CH);
        aggregate256_kernel<true><<<aggBlocks, 256>>>(b2, N);
    }
    // --- layer 3: fp16 MMA GEMM (BN=64, out 40) + fused agg/softmax ---
    {
        dim3 grid(1, mBlocks);
        gemm_h16_kernel<64, 1, 2><<<grid, 256>>>(N, OUTCH, OUTCH);
        agg40_softmax_kernel<<<N, 64>>>(b3, out, N);
    }
}

// round 9
// speedup vs baseline: 4.1520x; 1.0943x over previous
#include <cuda_runtime.h>
#include <cuda_fp16.h>
#include <math.h>
#include <stdint.h>

// ---------------------------------------------------------------------------
// GCN (3-layer) on 100k nodes / 1.6M edges.  edge_index arrives int32.
// R9: no convert_x (GEMM1 reads fp32 x, converts in-smem); packed (src,norm)
// int2 edges; ldmatrix fragment loads; streaming stores for agg16.
// ---------------------------------------------------------------------------

#define CH 256
#define OUTCH 40
#define N_NODES_MAX 100000
#define N_EDGES_MAX 1600000
#define SCAN_CHUNK 1024

__device__ __align__(16) __half g_h16[(size_t)N_NODES_MAX * CH];    // 50 MB
__device__ __align__(16) __half g_agg16[(size_t)N_NODES_MAX * CH];  // 50 MB
__device__ __align__(16) __half g_w1t[CH * CH];      // [n][k] transposed
__device__ __align__(16) __half g_w2t[CH * CH];
__device__ __align__(16) __half g_w3t[64 * CH];      // padded to 64 rows
__device__ int   g_cnt[N_NODES_MAX];
__device__ int   g_rowptr[N_NODES_MAX + 1];
__device__ int   g_wptr[N_NODES_MAX];
__device__ float g_dinv[N_NODES_MAX];
__device__ __align__(8) int2 g_edge[N_EDGES_MAX];    // (src, norm bits)
__device__ int   g_blocksum[128];
__device__ int   g_blockoff[128];

// ------------------------- CSR build -------------------------

__global__ void zero_cnt_kernel(int n) {
    int i = blockIdx.x * blockDim.x + threadIdx.x;
    if (i < n) g_cnt[i] = 0;
}
__global__ void hist_kernel(const int* __restrict__ ei, int E) {
    int e = blockIdx.x * blockDim.x + threadIdx.x;
    if (e < E) atomicAdd(&g_cnt[ei[E + e]], 1);
}
__global__ void scan_partial_kernel(int n) {
    __shared__ int warpsum[8];
    int base = blockIdx.x * SCAN_CHUNK + threadIdx.x * 4;
    int s = 0;
#pragma unroll
    for (int j = 0; j < 4; j++) { int i = base + j; if (i < n) s += g_cnt[i]; }
    int lane = threadIdx.x & 31, w = threadIdx.x >> 5;
#pragma unroll
    for (int off = 16; off > 0; off >>= 1) s += __shfl_xor_sync(0xFFFFFFFF, s, off);
    if (lane == 0) warpsum[w] = s;
    __syncthreads();
    if (threadIdx.x == 0) {
        int t = 0;
#pragma unroll
        for (int k = 0; k < 8; k++) t += warpsum[k];
        g_blocksum[blockIdx.x] = t;
    }
}
__global__ void scan_blocks_kernel(int nb) {
    int t = threadIdx.x;
    int v = (t < nb) ? g_blocksum[t] : 0;
    int orig = v;
    int lane = t & 31, w = t >> 5;
#pragma unroll
    for (int off = 1; off < 32; off <<= 1) {
        int u = __shfl_up_sync(0xFFFFFFFF, v, off);
        if (lane >= off) v += u;
    }
    __shared__ int ws[4];
    if (lane == 31) ws[w] = v;
    __syncthreads();
    int add = 0;
    for (int k = 0; k < w; k++) add += ws[k];
    if (t < nb) g_blockoff[t] = v + add - orig;
}
__global__ void scan_emit_kernel(int n, int E) {
    __shared__ int warpincl[8];
    int base = blockIdx.x * SCAN_CHUNK + threadIdx.x * 4;
    int c[4];
    int s = 0;
#pragma unroll
    for (int j = 0; j < 4; j++) {
        int i = base + j;
        c[j] = (i < n) ? g_cnt[i] : 0;
        s += c[j];
    }
    int lane = threadIdx.x & 31, w = threadIdx.x >> 5;
    int v = s;
#pragma unroll
    for (int off = 1; off < 32; off <<= 1) {
        int u = __shfl_up_sync(0xFFFFFFFF, v, off);
        if (lane >= off) v += u;
    }
    if (lane == 31) warpincl[w] = v;
    __syncthreads();
    int add = 0;
    for (int k = 0; k < w; k++) add += warpincl[k];
    int run = g_blockoff[blockIdx.x] + add + v - s;
#pragma unroll
    for (int j = 0; j < 4; j++) {
        int i = base + j;
        if (i < n) {
            g_rowptr[i] = run;
            g_wptr[i]   = run;
            g_dinv[i]   = rsqrtf((float)c[j] + 1.0f);
            run += c[j];
        }
    }
    if (blockIdx.x == 0 && threadIdx.x == 0) g_rowptr[n] = E;
}
__global__ void scatter_kernel(const int* __restrict__ ei, int E) {
    int e = blockIdx.x * blockDim.x + threadIdx.x;
    if (e < E) {
        int s = ei[e];
        int d = ei[E + e];
        int pos = atomicAdd(&g_wptr[d], 1);
        float norm = g_dinv[s] * g_dinv[d];
        g_edge[pos] = make_int2(s, __float_as_int(norm));
    }
}

// W1,W2 [k][n] fp32 -> [n][k] fp16; W3 [k][40] -> [64][k] fp16 (zero-padded)
__global__ void convert_w_kernel(const float* __restrict__ W1,
                                 const float* __restrict__ W2,
                                 const float* __restrict__ W3) {
    int n = blockIdx.x;
    int k = threadIdx.x;
    g_w1t[n * 256 + k] = __float2half_rn(__ldg(&W1[k * 256 + n]));
    g_w2t[n * 256 + k] = __float2half_rn(__ldg(&W2[k * 256 + n]));
    if (n < 64)
        g_w3t[n * 256 + k] = __float2half_rn(n < OUTCH ? __ldg(&W3[k * OUTCH + n]) : 0.f);
}

// ------------------- fp16 mma GEMM: C[M,*] = A[M,256] @ W^T -----------------
// BM=128, BN=128 or 64, BK=16. 8 warps 2(M)x4(N); warp tile 64 x BN/4.
// smem [row][24 halves]; fragment loads via ldmatrix.x4.
// ASEL: 0 = fp32 x (param), 1 = fp16 g_agg16.  WSEL: 0/1/2 = w1t/w2t/w3t.

#define HSTR 24

__device__ __forceinline__ uint32_t smem_cast(const void* p) {
    return (uint32_t)__cvta_generic_to_shared(p);
}

template <int BN, int ASEL, int WSEL>
__global__ __launch_bounds__(256, 2) void gemm_h16_kernel(
    const float* __restrict__ Xf, int M, int NOUT, int OS)
{
    const __half* Bt = (WSEL == 0) ? g_w1t : (WSEL == 1) ? g_w2t : g_w3t;
    constexpr int NTN = BN / 32;

    __shared__ __half As[2][128][HSTR];
    __shared__ __half Bs[2][BN][HSTR];
    constexpr uint32_t ABUF = 128 * HSTR * 2;
    constexpr uint32_t BBUF = BN * HSTR * 2;

    const int tid  = threadIdx.x;
    const int wid  = tid >> 5;
    const int lane = tid & 31;
    const int grp  = lane >> 2;
    const int tig  = lane & 3;
    const int wm   = wid & 1;
    const int wn   = wid >> 1;
    const int m0   = blockIdx.y * 128;
    const int n0   = blockIdx.x * BN;

    const int row = tid >> 1;
    const int kc  = tid & 1;

    // ldmatrix lane addressing
    const int lg   = lane >> 3;        // 0..3 matrix group
    const int lr   = lane & 7;         // row within matrix
    // A: row = wm*64 + mt*16 + (lg&1)*8 + lr, col = (lg>>1)*8
    uint32_t aAddrBase = smem_cast(&As[0][wm * 64 + (lg & 1) * 8 + lr][(lg >> 1) * 8]);
    // B (pair p): row = wn*(BN/4) + (2p + (lg>>1))*8 + lr, col = (lg&1)*8
    uint32_t bAddrBase = smem_cast(&Bs[0][wn * (BN / 4) + (lg >> 1) * 8 + lr][(lg & 1) * 8]);

    uint4 aH; float4 aF0, aF1; uint4 bG;
    auto loadG = [&](int k0) {
        int gm = m0 + row;
        if (ASEL == 0) {
            if (gm < M) {
                aF0 = __ldg((const float4*)(Xf + (size_t)gm * 256 + k0 + kc * 8));
                aF1 = __ldg((const float4*)(Xf + (size_t)gm * 256 + k0 + kc * 8 + 4));
            } else {
                aF0 = aF1 = make_float4(0.f, 0.f, 0.f, 0.f);
            }
        } else {
            aH = (gm < M) ? __ldg((const uint4*)(g_agg16 + (size_t)gm * 256 + k0 + kc * 8))
                          : make_uint4(0u, 0u, 0u, 0u);
        }
        if (BN == 128 || tid < BN * 2)
            bG = __ldg((const uint4*)(Bt + (size_t)(n0 + row) * 256 + k0 + kc * 8));
    };
    auto storeS = [&](int buf) {
        if (ASEL == 0) {
            uint4 v;
            __half2* p = (__half2*)&v;
            p[0] = __floats2half2_rn(aF0.x, aF0.y);
            p[1] = __floats2half2_rn(aF0.z, aF0.w);
            p[2] = __floats2half2_rn(aF1.x, aF1.y);
            p[3] = __floats2half2_rn(aF1.z, aF1.w);
            *(uint4*)&As[buf][row][kc * 8] = v;
        } else {
            *(uint4*)&As[buf][row][kc * 8] = aH;
        }
        if (BN == 128 || tid < BN * 2)
            *(uint4*)&Bs[buf][row][kc * 8] = bG;
    };

    float acc[4][NTN][4];
#pragma unroll
    for (int mt = 0; mt < 4; mt++)
#pragma unroll
        for (int nt = 0; nt < NTN; nt++)
#pragma unroll
            for (int r = 0; r < 4; r++) acc[mt][nt][r] = 0.0f;

    loadG(0);
    storeS(0);
    __syncthreads();

    const int NT = 256 / 16;
    for (int kt = 0; kt < NT; kt++) {
        const int cur = kt & 1;
        if (kt + 1 < NT) loadG((kt + 1) * 16);

        uint32_t aOff = aAddrBase + cur * ABUF;
        uint32_t bOff = bAddrBase + cur * BBUF;
        uint32_t af[4][4], bf[NTN][2];
#pragma unroll
        for (int mt = 0; mt < 4; mt++) {
            asm volatile(
                "ldmatrix.sync.aligned.m8n8.x4.shared.b16 {%0,%1,%2,%3}, [%4];"
                : "=r"(af[mt][0]), "=r"(af[mt][1]), "=r"(af[mt][2]), "=r"(af[mt][3])
                : "r"(aOff + mt * (16 * HSTR * 2)));
        }
#pragma unroll
        for (int p = 0; p < NTN / 2; p++) {
            asm volatile(
                "ldmatrix.sync.aligned.m8n8.x4.shared.b16 {%0,%1,%2,%3}, [%4];"
                : "=r"(bf[2 * p][0]), "=r"(bf[2 * p][1]),
                  "=r"(bf[2 * p + 1][0]), "=r"(bf[2 * p + 1][1])
                : "r"(bOff + p * (16 * HSTR * 2)));
        }
#pragma unroll
        for (int mt = 0; mt < 4; mt++)
#pragma unroll
            for (int nt = 0; nt < NTN; nt++) {
                asm volatile(
                    "mma.sync.aligned.m16n8k16.row.col.f32.f16.f16.f32 "
                    "{%0,%1,%2,%3}, {%4,%5,%6,%7}, {%8,%9}, {%0,%1,%2,%3};"
                    : "+f"(acc[mt][nt][0]), "+f"(acc[mt][nt][1]),
                      "+f"(acc[mt][nt][2]), "+f"(acc[mt][nt][3])
                    : "r"(af[mt][0]), "r"(af[mt][1]), "r"(af[mt][2]), "r"(af[mt][3]),
                      "r"(bf[nt][0]), "r"(bf[nt][1]));
            }
        if (kt + 1 < NT) storeS(cur ^ 1);
        __syncthreads();
    }

    // epilogue -> g_h16 (row stride OS), guard col < NOUT
#pragma unroll
    for (int mt = 0; mt < 4; mt++) {
        int gm = m0 + wm * 64 + mt * 16 + grp;
#pragma unroll
        for (int nt = 0; nt < NTN; nt++) {
            int gn = n0 + wn * (BN / 4) + nt * 8 + tig * 2;
            if (gn < NOUT) {
                if (gm < M)
                    *(__half2*)(g_h16 + (size_t)gm * OS + gn) =
                        __floats2half2_rn(acc[mt][nt][0], acc[mt][nt][1]);
                if (gm + 8 < M)
                    *(__half2*)(g_h16 + (size_t)(gm + 8) * OS + gn) =
                        __floats2half2_rn(acc[mt][nt][2], acc[mt][nt][3]);
            }
        }
    }
}

// ------------------- Aggregation 256-ch: h16 gather -> agg16 ----------------
// 8 nodes/block, 32 threads/node; thread gathers uint4 = 8 halves; unroll 4.
template <bool RELU>
__global__ __launch_bounds__(256) void aggregate256_kernel(
    const float* __restrict__ bias, int n)
{
    const int node = blockIdx.x * 8 + (threadIdx.x >> 5);
    const int c8   = threadIdx.x & 31;
    if (node >= n) return;
    const uint4* h = (const uint4*)g_h16;
    const int beg = g_rowptr[node];
    const int end = g_rowptr[node + 1];
    const float di = g_dinv[node];
    const float dii = di * di;

    float acc[8];
    {
        uint4 v = h[(size_t)node * 32 + c8];
        const __half2* hp = (const __half2*)&v;
#pragma unroll
        for (int q = 0; q < 4; q++) {
            float2 f = __half22float2(hp[q]);
            acc[q * 2 + 0] = f.x * dii;
            acc[q * 2 + 1] = f.y * dii;
        }
    }

    int e = beg;
    for (; e + 4 <= end; e += 4) {
        int2 e0 = __ldg(&g_edge[e + 0]);
        int2 e1 = __ldg(&g_edge[e + 1]);
        int2 e2 = __ldg(&g_edge[e + 2]);
        int2 e3 = __ldg(&g_edge[e + 3]);
        uint4 v0 = __ldg(&h[(size_t)e0.x * 32 + c8]);
        uint4 v1 = __ldg(&h[(size_t)e1.x * 32 + c8]);
        uint4 v2 = __ldg(&h[(size_t)e2.x * 32 + c8]);
        uint4 v3 = __ldg(&h[(size_t)e3.x * 32 + c8]);
        float w0 = __int_as_float(e0.y), w1 = __int_as_float(e1.y);
        float w2 = __int_as_float(e2.y), w3 = __int_as_float(e3.y);
        const __half2* p0 = (const __half2*)&v0;
        const __half2* p1 = (const __half2*)&v1;
        const __half2* p2 = (const __half2*)&v2;
        const __half2* p3 = (const __half2*)&v3;
#pragma unroll
        for (int q = 0; q < 4; q++) {
            float2 f0 = __half22float2(p0[q]);
            float2 f1 = __half22float2(p1[q]);
            float2 f2 = __half22float2(p2[q]);
            float2 f3 = __half22float2(p3[q]);
            acc[q * 2 + 0] += w0 * f0.x + w1 * f1.x + w2 * f2.x + w3 * f3.x;
            acc[q * 2 + 1] += w0 * f0.y + w1 * f1.y + w2 * f2.y + w3 * f3.y;
        }
    }
    for (; e < end; e++) {
        int2 ed = __ldg(&g_edge[e]);
        uint4 v0 = __ldg(&h[(size_t)ed.x * 32 + c8]);
        float w0 = __int_as_float(ed.y);
        const __half2* p0 = (const __half2*)&v0;
#pragma unroll
        for (int q = 0; q < 4; q++) {
            float2 f0 = __half22float2(p0[q]);
            acc[q * 2 + 0] += w0 * f0.x;
            acc[q * 2 + 1] += w0 * f0.y;
        }
    }

    float4 b0 = __ldg((const float4*)(bias + c8 * 8));
    float4 b1 = __ldg((const float4*)(bias + c8 * 8 + 4));
    acc[0] += b0.x; acc[1] += b0.y; acc[2] += b0.z; acc[3] += b0.w;
    acc[4] += b1.x; acc[5] += b1.y; acc[6] += b1.z; acc[7] += b1.w;
    if (RELU) {
#pragma unroll
        for (int q = 0; q < 8; q++) acc[q] = fmaxf(acc[q], 0.0f);
    }
    uint4 ov;
    __half2* op = (__half2*)&ov;
    op[0] = __floats2half2_rn(acc[0], acc[1]);
    op[1] = __floats2half2_rn(acc[2], acc[3]);
    op[2] = __floats2half2_rn(acc[4], acc[5]);
    op[3] = __floats2half2_rn(acc[6], acc[7]);
    // streaming store: agg lines are read-once by the next GEMM
    __stcs((float4*)((uint4*)g_agg16 + (size_t)node * 32 + c8), *(float4*)&ov);
}

// ---------- fused layer-3 aggregation (40 ch) + log_softmax -----------------

__global__ __launch_bounds__(64) void agg40_softmax_kernel(
    const float* __restrict__ bias, float* __restrict__ out, int n)
{
    __shared__ float sv[OUTCH];
    const int node = blockIdx.x;
    const int c = threadIdx.x;
    if (c < OUTCH) {
        const int beg = g_rowptr[node];
        const int end = g_rowptr[node + 1];
        const float di = g_dinv[node];
        float acc = __half2float(g_h16[(size_t)node * OUTCH + c]) * di * di;
        for (int e = beg; e < end; e++) {
            int2 ed = __ldg(&g_edge[e]);
            acc += __int_as_float(ed.y) *
                   __half2float(__ldg(&g_h16[(size_t)ed.x * OUTCH + c]));
        }
        sv[c] = acc + bias[c];
    }
    __syncthreads();
    if (threadIdx.x < 32) {
        int lane = threadIdx.x;
        float x0 = sv[lane];
        float x1 = (lane < OUTCH - 32) ? sv[32 + lane] : -INFINITY;
        float m = fmaxf(x0, x1);
#pragma unroll
        for (int off = 16; off > 0; off >>= 1)
            m = fmaxf(m, __shfl_xor_sync(0xFFFFFFFF, m, off));
        float s = expf(x0 - m) + ((lane < OUTCH - 32) ? expf(x1 - m) : 0.0f);
#pragma unroll
        for (int off = 16; off > 0; off >>= 1)
            s += __shfl_xor_sync(0xFFFFFFFF, s, off);
        float lse = logf(s);
        float* o = out + (size_t)node * OUTCH;
        o[lane] = x0 - m - lse;
        if (lane < OUTCH - 32) o[32 + lane] = x1 - m - lse;
    }
}

// ------------------------- launch -------------------------

extern "C" void kernel_launch(void* const* d_in, const int* in_sizes, int n_in,
                              void* d_out, int out_size)
{
    const float* x  = (const float*)d_in[0];
    const int*   ei = (const int*)d_in[1];       // int32
    const float* W1 = (const float*)d_in[2];
    const float* b1 = (const float*)d_in[3];
    const float* W2 = (const float*)d_in[4];
    const float* b2 = (const float*)d_in[5];
    const float* W3 = (const float*)d_in[6];
    const float* b3 = (const float*)d_in[7];
    float* out = (float*)d_out;

    const int N = in_sizes[0] / CH;       // 100000
    const int E = in_sizes[1] / 2;        // 1600000
    const int NB = (N + SCAN_CHUNK - 1) / SCAN_CHUNK;

    // --- CSR build + weight conversion ---
    zero_cnt_kernel<<<(N + 255) / 256, 256>>>(N);
    hist_kernel<<<(E + 255) / 256, 256>>>(ei, E);
    scan_partial_kernel<<<NB, 256>>>(N);
    scan_blocks_kernel<<<1, 128>>>(NB);
    scan_emit_kernel<<<NB, 256>>>(N, E);
    scatter_kernel<<<(E + 255) / 256, 256>>>(ei, E);
    convert_w_kernel<<<256, 256>>>(W1, W2, W3);

    const int mBlocks   = (N + 127) / 128;         // 782
    const int aggBlocks = (N + 7) / 8;

    // --- layer 1 (fp32 A = x) ---
    {
        dim3 grid(2, mBlocks);
        gemm_h16_kernel<128, 0, 0><<<grid, 256>>>(x, N, CH, CH);
        aggregate256_kernel<true><<<aggBlocks, 256>>>(b1, N);
    }
    // --- layer 2 ---
    {
        dim3 grid(2, mBlocks);
        gemm_h16_kernel<128, 1, 1><<<grid, 256>>>(nullptr, N, CH, CH);
        aggregate256_kernel<true><<<aggBlocks, 256>>>(b2, N);
    }
    // --- layer 3: fp16 MMA GEMM (BN=64, out 40) + fused agg/softmax ---
    {
        dim3 grid(1, mBlocks);
        gemm_h16_kernel<64, 1, 2><<<grid, 256>>>(nullptr, N, OUTCH, OUTCH);
        agg40_softmax_kernel<<<N, 64>>>(b3, out, N);
    }
}

// round 10
// speedup vs baseline: 4.2649x; 1.0272x over previous
#include <cuda_runtime.h>
#include <cuda_fp16.h>
#include <math.h>
#include <stdint.h>

// ---------------------------------------------------------------------------
// GCN (3-layer) on 100k nodes / 1.6M edges.  edge_index arrives int32.
// R10: graph-level concurrency — CSR build chain runs in parallel with
// convert_w + GEMM1 via stream fork/join inside capture. Kernels unchanged
// from the R9-validated versions.
// ---------------------------------------------------------------------------

#define CH 256
#define OUTCH 40
#define N_NODES_MAX 100000
#define N_EDGES_MAX 1600000
#define SCAN_CHUNK 1024

__device__ __align__(16) __half g_h16[(size_t)N_NODES_MAX * CH];    // 50 MB
__device__ __align__(16) __half g_agg16[(size_t)N_NODES_MAX * CH];  // 50 MB
__device__ __align__(16) __half g_w1t[CH * CH];      // [n][k] transposed
__device__ __align__(16) __half g_w2t[CH * CH];
__device__ __align__(16) __half g_w3t[64 * CH];      // padded to 64 rows
__device__ int   g_cnt[N_NODES_MAX];
__device__ int   g_rowptr[N_NODES_MAX + 1];
__device__ int   g_wptr[N_NODES_MAX];
__device__ float g_dinv[N_NODES_MAX];
__device__ __align__(8) int2 g_edge[N_EDGES_MAX];    // (src, norm bits)
__device__ int   g_blocksum[128];
__device__ int   g_blockoff[128];

// ------------------------- CSR build -------------------------

__global__ void zero_cnt_kernel(int n) {
    int i = blockIdx.x * blockDim.x + threadIdx.x;
    if (i < n) g_cnt[i] = 0;
}
__global__ void hist_kernel(const int* __restrict__ ei, int E) {
    int e = blockIdx.x * blockDim.x + threadIdx.x;
    if (e < E) atomicAdd(&g_cnt[ei[E + e]], 1);
}
__global__ void scan_partial_kernel(int n) {
    __shared__ int warpsum[8];
    int base = blockIdx.x * SCAN_CHUNK + threadIdx.x * 4;
    int s = 0;
#pragma unroll
    for (int j = 0; j < 4; j++) { int i = base + j; if (i < n) s += g_cnt[i]; }
    int lane = threadIdx.x & 31, w = threadIdx.x >> 5;
#pragma unroll
    for (int off = 16; off > 0; off >>= 1) s += __shfl_xor_sync(0xFFFFFFFF, s, off);
    if (lane == 0) warpsum[w] = s;
    __syncthreads();
    if (threadIdx.x == 0) {
        int t = 0;
#pragma unroll
        for (int k = 0; k < 8; k++) t += warpsum[k];
        g_blocksum[blockIdx.x] = t;
    }
}
__global__ void scan_blocks_kernel(int nb) {
    int t = threadIdx.x;
    int v = (t < nb) ? g_blocksum[t] : 0;
    int orig = v;
    int lane = t & 31, w = t >> 5;
#pragma unroll
    for (int off = 1; off < 32; off <<= 1) {
        int u = __shfl_up_sync(0xFFFFFFFF, v, off);
        if (lane >= off) v += u;
    }
    __shared__ int ws[4];
    if (lane == 31) ws[w] = v;
    __syncthreads();
    int add = 0;
    for (int k = 0; k < w; k++) add += ws[k];
    if (t < nb) g_blockoff[t] = v + add - orig;
}
__global__ void scan_emit_kernel(int n, int E) {
    __shared__ int warpincl[8];
    int base = blockIdx.x * SCAN_CHUNK + threadIdx.x * 4;
    int c[4];
    int s = 0;
#pragma unroll
    for (int j = 0; j < 4; j++) {
        int i = base + j;
        c[j] = (i < n) ? g_cnt[i] : 0;
        s += c[j];
    }
    int lane = threadIdx.x & 31, w = threadIdx.x >> 5;
    int v = s;
#pragma unroll
    for (int off = 1; off < 32; off <<= 1) {
        int u = __shfl_up_sync(0xFFFFFFFF, v, off);
        if (lane >= off) v += u;
    }
    if (lane == 31) warpincl[w] = v;
    __syncthreads();
    int add = 0;
    for (int k = 0; k < w; k++) add += warpincl[k];
    int run = g_blockoff[blockIdx.x] + add + v - s;
#pragma unroll
    for (int j = 0; j < 4; j++) {
        int i = base + j;
        if (i < n) {
            g_rowptr[i] = run;
            g_wptr[i]   = run;
            g_dinv[i]   = rsqrtf((float)c[j] + 1.0f);
            run += c[j];
        }
    }
    if (blockIdx.x == 0 && threadIdx.x == 0) g_rowptr[n] = E;
}
__global__ void scatter_kernel(const int* __restrict__ ei, int E) {
    int e = blockIdx.x * blockDim.x + threadIdx.x;
    if (e < E) {
        int s = ei[e];
        int d = ei[E + e];
        int pos = atomicAdd(&g_wptr[d], 1);
        float norm = g_dinv[s] * g_dinv[d];
        g_edge[pos] = make_int2(s, __float_as_int(norm));
    }
}

// W1,W2 [k][n] fp32 -> [n][k] fp16; W3 [k][40] -> [64][k] fp16 (zero-padded)
__global__ void convert_w_kernel(const float* __restrict__ W1,
                                 const float* __restrict__ W2,
                                 const float* __restrict__ W3) {
    int n = blockIdx.x;
    int k = threadIdx.x;
    g_w1t[n * 256 + k] = __float2half_rn(__ldg(&W1[k * 256 + n]));
    g_w2t[n * 256 + k] = __float2half_rn(__ldg(&W2[k * 256 + n]));
    if (n < 64)
        g_w3t[n * 256 + k] = __float2half_rn(n < OUTCH ? __ldg(&W3[k * OUTCH + n]) : 0.f);
}

// ------------------- fp16 mma GEMM: C[M,*] = A[M,256] @ W^T -----------------
// BM=128, BN=128 or 64, BK=16. 8 warps 2(M)x4(N); warp tile 64 x BN/4.
// smem [row][24 halves]; fragment loads via ldmatrix.x4.
// ASEL: 0 = fp32 x (param), 1 = fp16 g_agg16.  WSEL: 0/1/2 = w1t/w2t/w3t.

#define HSTR 24

__device__ __forceinline__ uint32_t smem_cast(const void* p) {
    return (uint32_t)__cvta_generic_to_shared(p);
}

template <int BN, int ASEL, int WSEL>
__global__ __launch_bounds__(256, 2) void gemm_h16_kernel(
    const float* __restrict__ Xf, int M, int NOUT, int OS)
{
    const __half* Bt = (WSEL == 0) ? g_w1t : (WSEL == 1) ? g_w2t : g_w3t;
    constexpr int NTN = BN / 32;

    __shared__ __half As[2][128][HSTR];
    __shared__ __half Bs[2][BN][HSTR];
    constexpr uint32_t ABUF = 128 * HSTR * 2;
    constexpr uint32_t BBUF = BN * HSTR * 2;

    const int tid  = threadIdx.x;
    const int wid  = tid >> 5;
    const int lane = tid & 31;
    const int grp  = lane >> 2;
    const int tig  = lane & 3;
    const int wm   = wid & 1;
    const int wn   = wid >> 1;
    const int m0   = blockIdx.y * 128;
    const int n0   = blockIdx.x * BN;

    const int row = tid >> 1;
    const int kc  = tid & 1;

    const int lg   = lane >> 3;
    const int lr   = lane & 7;
    uint32_t aAddrBase = smem_cast(&As[0][wm * 64 + (lg & 1) * 8 + lr][(lg >> 1) * 8]);
    uint32_t bAddrBase = smem_cast(&Bs[0][wn * (BN / 4) + (lg >> 1) * 8 + lr][(lg & 1) * 8]);

    uint4 aH; float4 aF0, aF1; uint4 bG;
    auto loadG = [&](int k0) {
        int gm = m0 + row;
        if (ASEL == 0) {
            if (gm < M) {
                aF0 = __ldg((const float4*)(Xf + (size_t)gm * 256 + k0 + kc * 8));
                aF1 = __ldg((const float4*)(Xf + (size_t)gm * 256 + k0 + kc * 8 + 4));
            } else {
                aF0 = aF1 = make_float4(0.f, 0.f, 0.f, 0.f);
            }
        } else {
            aH = (gm < M) ? __ldg((const uint4*)(g_agg16 + (size_t)gm * 256 + k0 + kc * 8))
                          : make_uint4(0u, 0u, 0u, 0u);
        }
        if (BN == 128 || tid < BN * 2)
            bG = __ldg((const uint4*)(Bt + (size_t)(n0 + row) * 256 + k0 + kc * 8));
    };
    auto storeS = [&](int buf) {
        if (ASEL == 0) {
            uint4 v;
            __half2* p = (__half2*)&v;
            p[0] = __floats2half2_rn(aF0.x, aF0.y);
            p[1] = __floats2half2_rn(aF0.z, aF0.w);
            p[2] = __floats2half2_rn(aF1.x, aF1.y);
            p[3] = __floats2half2_rn(aF1.z, aF1.w);
            *(uint4*)&As[buf][row][kc * 8] = v;
        } else {
            *(uint4*)&As[buf][row][kc * 8] = aH;
        }
        if (BN == 128 || tid < BN * 2)
            *(uint4*)&Bs[buf][row][kc * 8] = bG;
    };

    float acc[4][NTN][4];
#pragma unroll
    for (int mt = 0; mt < 4; mt++)
#pragma unroll
        for (int nt = 0; nt < NTN; nt++)
#pragma unroll
            for (int r = 0; r < 4; r++) acc[mt][nt][r] = 0.0f;

    loadG(0);
    storeS(0);
    __syncthreads();

    const int NT = 256 / 16;
    for (int kt = 0; kt < NT; kt++) {
        const int cur = kt & 1;
        if (kt + 1 < NT) loadG((kt + 1) * 16);

        uint32_t aOff = aAddrBase + cur * ABUF;
        uint32_t bOff = bAddrBase + cur * BBUF;
        uint32_t af[4][4], bf[NTN][2];
#pragma unroll
        for (int mt = 0; mt < 4; mt++) {
            asm volatile(
                "ldmatrix.sync.aligned.m8n8.x4.shared.b16 {%0,%1,%2,%3}, [%4];"
                : "=r"(af[mt][0]), "=r"(af[mt][1]), "=r"(af[mt][2]), "=r"(af[mt][3])
                : "r"(aOff + mt * (16 * HSTR * 2)));
        }
#pragma unroll
        for (int p = 0; p < NTN / 2; p++) {
            asm volatile(
                "ldmatrix.sync.aligned.m8n8.x4.shared.b16 {%0,%1,%2,%3}, [%4];"
                : "=r"(bf[2 * p][0]), "=r"(bf[2 * p][1]),
                  "=r"(bf[2 * p + 1][0]), "=r"(bf[2 * p + 1][1])
                : "r"(bOff + p * (16 * HSTR * 2)));
        }
#pragma unroll
        for (int mt = 0; mt < 4; mt++)
#pragma unroll
            for (int nt = 0; nt < NTN; nt++) {
                asm volatile(
                    "mma.sync.aligned.m16n8k16.row.col.f32.f16.f16.f32 "
                    "{%0,%1,%2,%3}, {%4,%5,%6,%7}, {%8,%9}, {%0,%1,%2,%3};"
                    : "+f"(acc[mt][nt][0]), "+f"(acc[mt][nt][1]),
                      "+f"(acc[mt][nt][2]), "+f"(acc[mt][nt][3])
                    : "r"(af[mt][0]), "r"(af[mt][1]), "r"(af[mt][2]), "r"(af[mt][3]),
                      "r"(bf[nt][0]), "r"(bf[nt][1]));
            }
        if (kt + 1 < NT) storeS(cur ^ 1);
        __syncthreads();
    }

#pragma unroll
    for (int mt = 0; mt < 4; mt++) {
        int gm = m0 + wm * 64 + mt * 16 + grp;
#pragma unroll
        for (int nt = 0; nt < NTN; nt++) {
            int gn = n0 + wn * (BN / 4) + nt * 8 + tig * 2;
            if (gn < NOUT) {
                if (gm < M)
                    *(__half2*)(g_h16 + (size_t)gm * OS + gn) =
                        __floats2half2_rn(acc[mt][nt][0], acc[mt][nt][1]);
                if (gm + 8 < M)
                    *(__half2*)(g_h16 + (size_t)(gm + 8) * OS + gn) =
                        __floats2half2_rn(acc[mt][nt][2], acc[mt][nt][3]);
            }
        }
    }
}

// ------------------- Aggregation 256-ch: h16 gather -> agg16 ----------------
template <bool RELU>
__global__ __launch_bounds__(256) void aggregate256_kernel(
    const float* __restrict__ bias, int n)
{
    const int node = blockIdx.x * 8 + (threadIdx.x >> 5);
    const int c8   = threadIdx.x & 31;
    if (node >= n) return;
    const uint4* h = (const uint4*)g_h16;
    const int beg = g_rowptr[node];
    const int end = g_rowptr[node + 1];
    const float di = g_dinv[node];
    const float dii = di * di;

    float acc[8];
    {
        uint4 v = h[(size_t)node * 32 + c8];
        const __half2* hp = (const __half2*)&v;
#pragma unroll
        for (int q = 0; q < 4; q++) {
            float2 f = __half22float2(hp[q]);
            acc[q * 2 + 0] = f.x * dii;
            acc[q * 2 + 1] = f.y * dii;
        }
    }

    int e = beg;
    for (; e + 4 <= end; e += 4) {
        int2 e0 = __ldg(&g_edge[e + 0]);
        int2 e1 = __ldg(&g_edge[e + 1]);
        int2 e2 = __ldg(&g_edge[e + 2]);
        int2 e3 = __ldg(&g_edge[e + 3]);
        uint4 v0 = __ldg(&h[(size_t)e0.x * 32 + c8]);
        uint4 v1 = __ldg(&h[(size_t)e1.x * 32 + c8]);
        uint4 v2 = __ldg(&h[(size_t)e2.x * 32 + c8]);
        uint4 v3 = __ldg(&h[(size_t)e3.x * 32 + c8]);
        float w0 = __int_as_float(e0.y), w1 = __int_as_float(e1.y);
        float w2 = __int_as_float(e2.y), w3 = __int_as_float(e3.y);
        const __half2* p0 = (const __half2*)&v0;
        const __half2* p1 = (const __half2*)&v1;
        const __half2* p2 = (const __half2*)&v2;
        const __half2* p3 = (const __half2*)&v3;
#pragma unroll
        for (int q = 0; q < 4; q++) {
            float2 f0 = __half22float2(p0[q]);
            float2 f1 = __half22float2(p1[q]);
            float2 f2 = __half22float2(p2[q]);
            float2 f3 = __half22float2(p3[q]);
            acc[q * 2 + 0] += w0 * f0.x + w1 * f1.x + w2 * f2.x + w3 * f3.x;
            acc[q * 2 + 1] += w0 * f0.y + w1 * f1.y + w2 * f2.y + w3 * f3.y;
        }
    }
    for (; e < end; e++) {
        int2 ed = __ldg(&g_edge[e]);
        uint4 v0 = __ldg(&h[(size_t)ed.x * 32 + c8]);
        float w0 = __int_as_float(ed.y);
        const __half2* p0 = (const __half2*)&v0;
#pragma unroll
        for (int q = 0; q < 4; q++) {
            float2 f0 = __half22float2(p0[q]);
            acc[q * 2 + 0] += w0 * f0.x;
            acc[q * 2 + 1] += w0 * f0.y;
        }
    }

    float4 b0 = __ldg((const float4*)(bias + c8 * 8));
    float4 b1 = __ldg((const float4*)(bias + c8 * 8 + 4));
    acc[0] += b0.x; acc[1] += b0.y; acc[2] += b0.z; acc[3] += b0.w;
    acc[4] += b1.x; acc[5] += b1.y; acc[6] += b1.z; acc[7] += b1.w;
    if (RELU) {
#pragma unroll
        for (int q = 0; q < 8; q++) acc[q] = fmaxf(acc[q], 0.0f);
    }
    uint4 ov;
    __half2* op = (__half2*)&ov;
    op[0] = __floats2half2_rn(acc[0], acc[1]);
    op[1] = __floats2half2_rn(acc[2], acc[3]);
    op[2] = __floats2half2_rn(acc[4], acc[5]);
    op[3] = __floats2half2_rn(acc[6], acc[7]);
    __stcs((float4*)((uint4*)g_agg16 + (size_t)node * 32 + c8), *(float4*)&ov);
}

// ---------- fused layer-3 aggregation (40 ch) + log_softmax -----------------

__global__ __launch_bounds__(64) void agg40_softmax_kernel(
    const float* __restrict__ bias, float* __restrict__ out, int n)
{
    __shared__ float sv[OUTCH];
    const int node = blockIdx.x;
    const int c = threadIdx.x;
    if (c < OUTCH) {
        const int beg = g_rowptr[node];
        const int end = g_rowptr[node + 1];
        const float di = g_dinv[node];
        float acc = __half2float(g_h16[(size_t)node * OUTCH + c]) * di * di;
        for (int e = beg; e < end; e++) {
            int2 ed = __ldg(&g_edge[e]);
            acc += __int_as_float(ed.y) *
                   __half2float(__ldg(&g_h16[(size_t)ed.x * OUTCH + c]));
        }
        sv[c] = acc + bias[c];
    }
    __syncthreads();
    if (threadIdx.x < 32) {
        int lane = threadIdx.x;
        float x0 = sv[lane];
        float x1 = (lane < OUTCH - 32) ? sv[32 + lane] : -INFINITY;
        float m = fmaxf(x0, x1);
#pragma unroll
        for (int off = 16; off > 0; off >>= 1)
            m = fmaxf(m, __shfl_xor_sync(0xFFFFFFFF, m, off));
        float s = expf(x0 - m) + ((lane < OUTCH - 32) ? expf(x1 - m) : 0.0f);
#pragma unroll
        for (int off = 16; off > 0; off >>= 1)
            s += __shfl_xor_sync(0xFFFFFFFF, s, off);
        float lse = logf(s);
        float* o = out + (size_t)node * OUTCH;
        o[lane] = x0 - m - lse;
        if (lane < OUTCH - 32) o[32 + lane] = x1 - m - lse;
    }
}

// ------------------------- launch -------------------------

extern "C" void kernel_launch(void* const* d_in, const int* in_sizes, int n_in,
                              void* d_out, int out_size)
{
    const float* x  = (const float*)d_in[0];
    const int*   ei = (const int*)d_in[1];       // int32
    const float* W1 = (const float*)d_in[2];
    const float* b1 = (const float*)d_in[3];
    const float* W2 = (const float*)d_in[4];
    const float* b2 = (const float*)d_in[5];
    const float* W3 = (const float*)d_in[6];
    const float* b3 = (const float*)d_in[7];
    float* out = (float*)d_out;

    const int N = in_sizes[0] / CH;       // 100000
    const int E = in_sizes[1] / 2;        // 1600000
    const int NB = (N + SCAN_CHUNK - 1) / SCAN_CHUNK;

    // one-time stream/event setup (first call is the uncaptured correctness
    // run; objects persist across graph capture + replays; no device memory)
    static cudaStream_t s2 = nullptr;
    static cudaEvent_t evFork = nullptr, evGemm = nullptr;
    if (s2 == nullptr) {
        cudaStreamCreateWithFlags(&s2, cudaStreamNonBlocking);
        cudaEventCreateWithFlags(&evFork, cudaEventDisableTiming);
        cudaEventCreateWithFlags(&evGemm, cudaEventDisableTiming);
    }

    const int mBlocks   = (N + 127) / 128;         // 782
    const int aggBlocks = (N + 7) / 8;

    // --- fork: convert_w + GEMM1 on s2, CSR build on the capture stream ---
    cudaEventRecord(evFork, 0);
    cudaStreamWaitEvent(s2, evFork, 0);
    convert_w_kernel<<<256, 256, 0, s2>>>(W1, W2, W3);
    {
        dim3 grid(2, mBlocks);
        gemm_h16_kernel<128, 0, 0><<<grid, 256, 0, s2>>>(x, N, CH, CH);
    }
    cudaEventRecord(evGemm, s2);

    zero_cnt_kernel<<<(N + 255) / 256, 256>>>(N);
    hist_kernel<<<(E + 255) / 256, 256>>>(ei, E);
    scan_partial_kernel<<<NB, 256>>>(N);
    scan_blocks_kernel<<<1, 128>>>(NB);
    scan_emit_kernel<<<NB, 256>>>(N, E);
    scatter_kernel<<<(E + 255) / 256, 256>>>(ei, E);

    // --- join: aggregate1 needs both CSR and GEMM1 ---
    cudaStreamWaitEvent(0, evGemm, 0);
    aggregate256_kernel<true><<<aggBlocks, 256>>>(b1, N);

    // --- layer 2 ---
    {
        dim3 grid(2, mBlocks);
        gemm_h16_kernel<128, 1, 1><<<grid, 256>>>(nullptr, N, CH, CH);
        aggregate256_kernel<true><<<aggBlocks, 256>>>(b2, N);
    }
    // --- layer 3: fp16 MMA GEMM (BN=64, out 40) + fused agg/softmax ---
    {
        dim3 grid(1, mBlocks);
        gemm_h16_kernel<64, 1, 2><<<grid, 256>>>(nullptr, N, OUTCH, OUTCH);
        agg40_softmax_kernel<<<N, 64>>>(b3, out, N);
    }
}